// round 9
// baseline (speedup 1.0000x reference)
#include <cuda_runtime.h>
#include <cuda.h>
#include <cuda_bf16.h>
#include <cstdint>

// Problem constants
#define BSZ   2048
#define D     2048
#define MM    6
#define THRESH 30
#define LAM   1.0e-4f
#define LDF   (MM*D)          // 12288
#define NITER (THRESH-1)      // 29

// GEMM tiling (R5 config): 128x256 CTA tile, TK=64 (SW128), 2 stages, 512 thr
#define TMt   128
#define TNt   256
#define TKt   64
#define KITERS (D / TKt)      // 32
#define A_BYTES (TMt * TKt * 2)              // 16384
#define W_BYTES (TNt * TKt * 2)              // 32768
#define STAGE_BYTES (2*A_BYTES + 2*W_BYTES)  // 98304
#define SMEM_TOTAL (2*STAGE_BYTES + 2048)

// ---------------- device scratch ----------------
__device__ float         g_F[(size_t)BSZ * MM * D];
__device__ float         g_G[(size_t)BSZ * MM * D];
__device__ __nv_bfloat16 g_Ahi[(size_t)BSZ * D];
__device__ __nv_bfloat16 g_Alo[(size_t)BSZ * D];
__device__ __nv_bfloat16 g_Whi[(size_t)D * D];        // [N,K] transposed
__device__ __nv_bfloat16 g_Wlo[(size_t)D * D];
__device__ float         g_alpha[BSZ * 8];
__device__ float         g_GGt[BSZ * 36];             // persistent Gram
__device__ double        g_norms[2 * NITER + 2];

// ---------------- PTX helpers ----------------
__device__ __forceinline__ uint32_t smem_u32(const void* p) {
    uint32_t a;
    asm("{ .reg .u64 t; cvta.to.shared.u64 t, %1; cvt.u32.u64 %0, t; }" : "=r"(a) : "l"(p));
    return a;
}
#define MBAR_INIT(a, c) asm volatile("mbarrier.init.shared.b64 [%0], %1;" :: "r"(a), "r"(c) : "memory")
#define MBAR_EXPECT_TX(a, b) asm volatile("mbarrier.arrive.expect_tx.shared.b64 _, [%0], %1;" :: "r"(a), "r"(b) : "memory")
#define MBAR_ARRIVE(a) asm volatile("mbarrier.arrive.shared.b64 _, [%0];" :: "r"(a) : "memory")
#define MBAR_WAIT(a, ph) do { \
    uint32_t _m = (a); uint32_t _p = (ph); \
    asm volatile("{\n\t.reg .pred P1;\n\tWL_%=:\n\t" \
        "mbarrier.try_wait.parity.acquire.cta.shared::cta.b64 P1, [%0], %1, 0x989680;\n\t" \
        "@P1 bra.uni WD_%=;\n\tbra.uni WL_%=;\n\tWD_%=:\n\t}" \
        :: "r"(_m), "r"(_p) : "memory"); \
} while (0)

__device__ __forceinline__ void tma2d(uint32_t dst, const CUtensorMap* tm, int x, int y, uint32_t bar) {
    asm volatile(
        "cp.async.bulk.tensor.2d.shared::cta.global.tile.mbarrier::complete_tx::bytes "
        "[%0], [%1, {%2, %3}], [%4];"
        :: "r"(dst), "l"(tm), "r"(x), "r"(y), "r"(bar) : "memory");
}

#define LDSM4(r, addr) \
    asm volatile("ldmatrix.sync.aligned.m8n8.x4.shared.b16 {%0,%1,%2,%3}, [%4];" \
        : "=r"((r)[0]), "=r"((r)[1]), "=r"((r)[2]), "=r"((r)[3]) : "r"(addr))

#define MMA16816(d, a, b0, b1) \
    asm volatile("mma.sync.aligned.m16n8k16.row.col.f32.bf16.bf16.f32 " \
        "{%0,%1,%2,%3}, {%4,%5,%6,%7}, {%8,%9}, {%0,%1,%2,%3};" \
        : "+f"((d)[0]), "+f"((d)[1]), "+f"((d)[2]), "+f"((d)[3]) \
        : "r"((a)[0]), "r"((a)[1]), "r"((a)[2]), "r"((a)[3]), "r"(b0), "r"(b1))

__device__ __forceinline__ void split32(float v, __nv_bfloat16& hi, __nv_bfloat16& lo) {
    hi = __float2bfloat16(v);
    lo = __float2bfloat16(v - __bfloat162float(hi));
}

__device__ __forceinline__ float fast_tanh(float x) {
    float ax = fabsf(x);
    float e = __expf(2.0f * ax);
    float r = 1.0f - __fdividef(2.0f, e + 1.0f);
    return copysignf(r, x);
}

// ---------------- HMMA GEMM: F = tanh(A @ W^T + bias); G = F - X; Gram row update; norms ----------------
__global__ __launch_bounds__(512, 1)
void mma_gemm_kernel(const __grid_constant__ CUtensorMap tmAhi,
                     const __grid_constant__ CUtensorMap tmAlo,
                     const __grid_constant__ CUtensorMap tmWhi,
                     const __grid_constant__ CUtensorMap tmWlo,
                     const float* __restrict__ bias,
                     float* __restrict__ C,          // F slot (row stride LDF)
                     const float* __restrict__ Xcur, // xnew slot
                     float* __restrict__ Gout,       // G slot (= Gall + up*D)
                     const float* __restrict__ Gall, // G base
                     float* __restrict__ GGt,        // [BSZ][36], row/col `up` pre-zeroed
                     int up,
                     double* norms_slot)             // may be null
{
    extern __shared__ char smem[];
    __shared__ float red[2][16];
    const uint32_t sb = smem_u32(smem);
    const uint32_t stage0 = (sb + 1024 + 1023) & ~1023u;   // SW128: 1024-aligned tiles
    const int tid = threadIdx.x;
    const int lane = tid & 31;
    const int w = tid >> 5;
    const int wm = w & 3;        // 4 warps over M (32 rows each)
    const int wn = w >> 2;       // 4 warps over N (64 cols each)
    const int bm = blockIdx.y * TMt;
    const int bn = blockIdx.x * TNt;

    const uint32_t FULL[2]  = { sb,      sb + 8  };
    const uint32_t EMPTY[2] = { sb + 16, sb + 24 };

    if (tid == 0) {
        MBAR_INIT(FULL[0], 1);  MBAR_INIT(FULL[1], 1);
        MBAR_INIT(EMPTY[0], 16); MBAR_INIT(EMPTY[1], 16);
    }
    __syncthreads();

    if (tid == 0) {
        #pragma unroll
        for (int s = 0; s < 2; s++) {
            uint32_t st = stage0 + s * STAGE_BYTES;
            MBAR_EXPECT_TX(FULL[s], STAGE_BYTES);
            tma2d(st,                         &tmAhi, s * TKt, bm, FULL[s]);
            tma2d(st + A_BYTES,               &tmAlo, s * TKt, bm, FULL[s]);
            tma2d(st + 2 * A_BYTES,           &tmWhi, s * TKt, bn, FULL[s]);
            tma2d(st + 2 * A_BYTES + W_BYTES, &tmWlo, s * TKt, bn, FULL[s]);
        }
    }

    float acc[2][8][4];
    #pragma unroll
    for (int mt = 0; mt < 2; mt++)
        #pragma unroll
        for (int nt = 0; nt < 8; nt++)
            #pragma unroll
            for (int q = 0; q < 4; q++) acc[mt][nt][q] = 0.f;

    const uint32_t xorv = (uint32_t)(lane & 7) << 4;
    const uint32_t a_r = lane & 15;
    const uint32_t a_b = (uint32_t)(lane >> 4) << 4;
    const uint32_t b_r = ((uint32_t)(lane >> 4) << 3) + (lane & 7);
    const uint32_t b_b = (uint32_t)((lane >> 3) & 1) << 4;

    for (int i = 0; i < KITERS; i++) {
        const int buf = i & 1;
        const int ph = (i >> 1) & 1;
        MBAR_WAIT(FULL[buf], ph);

        const uint32_t st = stage0 + buf * STAGE_BYTES;
        const uint32_t Ahi_b = st;
        const uint32_t Alo_b = st + A_BYTES;
        const uint32_t Whi_b = st + 2 * A_BYTES;
        const uint32_t Wlo_b = st + 2 * A_BYTES + W_BYTES;

        #pragma unroll
        for (int k16 = 0; k16 < 4; k16++) {
            uint32_t ahi[2][4], alo[2][4];
            #pragma unroll
            for (int mt = 0; mt < 2; mt++) {
                uint32_t R = wm * 32 + mt * 16 + a_r;
                uint32_t B = a_b + k16 * 32;
                uint32_t off = R * 128 + (B ^ xorv);
                LDSM4(ahi[mt], Ahi_b + off);
                LDSM4(alo[mt], Alo_b + off);
            }
            #pragma unroll
            for (int p = 0; p < 4; p++) {
                uint32_t R = wn * 64 + p * 16 + b_r;
                uint32_t B = b_b + k16 * 32;
                uint32_t off = R * 128 + (B ^ xorv);
                uint32_t wh[4], wl[4];
                LDSM4(wh, Whi_b + off);
                LDSM4(wl, Wlo_b + off);
                #pragma unroll
                for (int mt = 0; mt < 2; mt++) {
                    #pragma unroll
                    for (int q = 0; q < 2; q++) {
                        float* d = acc[mt][2 * p + q];
                        MMA16816(d, ahi[mt], wh[2 * q], wh[2 * q + 1]);
                        MMA16816(d, ahi[mt], wl[2 * q], wl[2 * q + 1]);
                        MMA16816(d, alo[mt], wh[2 * q], wh[2 * q + 1]);
                    }
                }
            }
        }
        if (lane == 0) MBAR_ARRIVE(EMPTY[buf]);
        if (tid == 0 && i + 2 < KITERS) {
            MBAR_WAIT(EMPTY[buf], ph);
            MBAR_EXPECT_TX(FULL[buf], STAGE_BYTES);
            int k0 = (i + 2) * TKt;
            tma2d(st,                         &tmAhi, k0, bm, FULL[buf]);
            tma2d(st + A_BYTES,               &tmAlo, k0, bm, FULL[buf]);
            tma2d(st + 2 * A_BYTES,           &tmWhi, k0, bn, FULL[buf]);
            tma2d(st + 2 * A_BYTES + W_BYTES, &tmWlo, k0, bn, FULL[buf]);
        }
    }

    // epilogue: bias+tanh -> F; g -> G; incremental Gram row `up`; norms
    const int r_in = lane >> 2;
    const int c_in = (lane & 3) * 2;
    float sg = 0.f, sf = 0.f;
    #pragma unroll
    for (int mt = 0; mt < 2; mt++) {
        const int row = bm + wm * 32 + mt * 16 + r_in;   // batch index (first of pair)
        float d0[6], d1[6];
        #pragma unroll
        for (int j = 0; j < 6; j++) { d0[j] = 0.f; d1[j] = 0.f; }
        #pragma unroll
        for (int nt = 0; nt < 8; nt++) {
            const int col = bn + wn * 64 + nt * 8 + c_in;
            float2 bb = *(const float2*)(bias + col);
            float v0 = fast_tanh(acc[mt][nt][0] + bb.x);
            float v1 = fast_tanh(acc[mt][nt][1] + bb.y);
            float v2 = fast_tanh(acc[mt][nt][2] + bb.x);
            float v3 = fast_tanh(acc[mt][nt][3] + bb.y);
            size_t o0 = (size_t)row * LDF + col;
            size_t o1 = (size_t)(row + 8) * LDF + col;
            float2 x0 = *(const float2*)(Xcur + o0);
            float2 x1 = *(const float2*)(Xcur + o1);
            float g0 = v0 - x0.x, g1 = v1 - x0.y;
            float g2 = v2 - x1.x, g3 = v3 - x1.y;
            *(float2*)(C + o0) = make_float2(v0, v1);
            *(float2*)(C + o1) = make_float2(v2, v3);
            *(float2*)(Gout + o0) = make_float2(g0, g1);
            *(float2*)(Gout + o1) = make_float2(g2, g3);
            sg += g0 * g0 + g1 * g1 + g2 * g2 + g3 * g3;
            sf += v0 * v0 + v1 * v1 + v2 * v2 + v3 * v3;
            #pragma unroll
            for (int j = 0; j < 6; j++) {
                if (j == up) {
                    d0[j] += g0 * g0 + g1 * g1;
                    d1[j] += g2 * g2 + g3 * g3;
                } else {
                    float2 a0 = *(const float2*)(Gall + (size_t)row * LDF + j * D + col);
                    float2 a1 = *(const float2*)(Gall + (size_t)(row + 8) * LDF + j * D + col);
                    d0[j] += g0 * a0.x + g1 * a0.y;
                    d1[j] += g2 * a1.x + g3 * a1.y;
                }
            }
        }
        // quad reduce (lanes sharing a row: same lane>>2) and accumulate into GGt
        #pragma unroll
        for (int j = 0; j < 6; j++) {
            float v0 = d0[j], v1 = d1[j];
            v0 += __shfl_xor_sync(0xFFFFFFFF, v0, 1);
            v0 += __shfl_xor_sync(0xFFFFFFFF, v0, 2);
            v1 += __shfl_xor_sync(0xFFFFFFFF, v1, 1);
            v1 += __shfl_xor_sync(0xFFFFFFFF, v1, 2);
            if ((lane & 3) == 0) {
                atomicAdd(&GGt[(size_t)row * 36 + up * 6 + j], v0);
                atomicAdd(&GGt[(size_t)(row + 8) * 36 + up * 6 + j], v1);
                if (j != up) {
                    atomicAdd(&GGt[(size_t)row * 36 + j * 6 + up], v0);
                    atomicAdd(&GGt[(size_t)(row + 8) * 36 + j * 6 + up], v1);
                }
            }
        }
    }
    if (norms_slot != nullptr) {
        #pragma unroll
        for (int s = 16; s > 0; s >>= 1) {
            sg += __shfl_xor_sync(0xFFFFFFFF, sg, s);
            sf += __shfl_xor_sync(0xFFFFFFFF, sf, s);
        }
        if (lane == 0) { red[0][w] = sg; red[1][w] = sf; }
        __syncthreads();
        if (w == 0 && lane < 16) {
            float a = red[0][lane], b = red[1][lane];
            #pragma unroll
            for (int s = 8; s > 0; s >>= 1) {
                a += __shfl_xor_sync(0xFFFF, a, s);
                b += __shfl_xor_sync(0xFFFF, b, s);
            }
            if (lane == 0) {
                atomicAdd(&norms_slot[0], (double)a);
                atomicAdd(&norms_slot[1], (double)b);
            }
        }
    }
}

// ---------------- bordered solve (one batch per thread) ----------------
__global__ void solve_kernel(const float* __restrict__ GGt, float* __restrict__ alpha, int n)
{
    int b = blockIdx.x * blockDim.x + threadIdx.x;
    if (b >= BSZ) return;
    const int s = n + 1;
    float H[7][7];
    float y[7];
    H[0][0] = 0.f; y[0] = 1.f;
    for (int i = 1; i < s; i++) { H[0][i] = 1.f; H[i][0] = 1.f; y[i] = 0.f; }
    const float* G = GGt + (size_t)b * 36;
    for (int i = 0; i < n; i++)
        for (int j = 0; j < n; j++)
            H[i + 1][j + 1] = G[i * 6 + j] + ((i == j) ? LAM : 0.f);

    for (int c = 0; c < s; c++) {
        int piv = c;
        float mx = fabsf(H[c][c]);
        for (int r = c + 1; r < s; r++) {
            float v = fabsf(H[r][c]);
            if (v > mx) { mx = v; piv = r; }
        }
        if (piv != c) {
            for (int cc = 0; cc < s; cc++) { float t = H[c][cc]; H[c][cc] = H[piv][cc]; H[piv][cc] = t; }
            float t = y[c]; y[c] = y[piv]; y[piv] = t;
        }
        float inv = 1.f / H[c][c];
        for (int r = c + 1; r < s; r++) {
            float f = H[r][c] * inv;
            if (f != 0.f) {
                for (int cc = c; cc < s; cc++) H[r][cc] -= f * H[c][cc];
                y[r] -= f * y[c];
            }
        }
    }
    float sol[7];
    for (int r = s - 1; r >= 0; r--) {
        float a = y[r];
        for (int cc = r + 1; cc < s; cc++) a -= H[r][cc] * sol[cc];
        sol[r] = a / H[r][r];
    }
    float* ab = alpha + b * 8;
    for (int i = 0; i < 6; i++) ab[i] = (i < n) ? sol[i + 1] : 0.f;
}

// ---------------- combine (float4) + bf16 split + zero GGt row/col `up` ----------------
__global__ __launch_bounds__(256)
void combine_kernel(const float* __restrict__ F, const float* __restrict__ alpha,
                    float* __restrict__ X,
                    __nv_bfloat16* __restrict__ Ahi, __nv_bfloat16* __restrict__ Alo,
                    float* __restrict__ GGt,
                    int n, int up)
{
    int b = blockIdx.y;
    int c4 = blockIdx.x * 256 + threadIdx.x;
    if (blockIdx.x == 0 && threadIdx.x < 6) {
        GGt[(size_t)b * 36 + up * 6 + threadIdx.x] = 0.f;
        GGt[(size_t)b * 36 + threadIdx.x * 6 + up] = 0.f;
    }
    const float4* Fb = (const float4*)(F + (size_t)b * LDF);
    const float* ab = alpha + b * 8;
    float4 acc = make_float4(0.f, 0.f, 0.f, 0.f);
#pragma unroll
    for (int j = 0; j < 6; j++) {
        if (j < n) {
            float a = ab[j];
            float4 f = Fb[j * 512 + c4];
            acc.x += a * f.x; acc.y += a * f.y; acc.z += a * f.z; acc.w += a * f.w;
        }
    }
    ((float4*)(X + (size_t)b * LDF + up * D))[c4] = acc;

    __nv_bfloat16 h0, l0, h1, l1, h2, l2, h3, l3;
    split32(acc.x, h0, l0); split32(acc.y, h1, l1);
    split32(acc.z, h2, l2); split32(acc.w, h3, l3);
    __nv_bfloat162* Ah = (__nv_bfloat162*)(Ahi + (size_t)b * D);
    __nv_bfloat162* Al = (__nv_bfloat162*)(Alo + (size_t)b * D);
    Ah[c4 * 2]     = __nv_bfloat162(h0, h1);
    Ah[c4 * 2 + 1] = __nv_bfloat162(h2, h3);
    Al[c4 * 2]     = __nv_bfloat162(l0, l1);
    Al[c4 * 2 + 1] = __nv_bfloat162(l2, l3);
}

// ---------------- W transpose + bf16 split ----------------
__global__ __launch_bounds__(1024)
void wsplit_kernel(const float* __restrict__ W,
                   __nv_bfloat16* __restrict__ Whi, __nv_bfloat16* __restrict__ Wlo)
{
    __shared__ float t[32][33];
    int n0 = blockIdx.x * 32, k0 = blockIdx.y * 32;
    t[threadIdx.y][threadIdx.x] = W[(size_t)(k0 + threadIdx.y) * D + n0 + threadIdx.x];
    __syncthreads();
    float v = t[threadIdx.x][threadIdx.y];
    __nv_bfloat16 hi, lo; split32(v, hi, lo);
    size_t o = (size_t)(n0 + threadIdx.y) * D + k0 + threadIdx.x;
    Whi[o] = hi; Wlo[o] = lo;
}

// ---------------- small utility kernels ----------------
__global__ void zero_norms_kernel(double* norms) {
    int i = threadIdx.x;
    if (i < 2 * NITER + 2) norms[i] = 0.0;
}

// X[:,0]=x0, A=split(x0), GGt[b][*]=0
__global__ void scatter_x0_kernel(const float* __restrict__ x0, float* __restrict__ X,
                                  __nv_bfloat16* __restrict__ Ahi, __nv_bfloat16* __restrict__ Alo,
                                  float* __restrict__ GGt) {
    int idx = blockIdx.x * blockDim.x + threadIdx.x;
    if (idx >= BSZ * D) return;
    int b = idx >> 11;
    int c = idx & (D - 1);
    float v = x0[idx];
    X[(size_t)b * LDF + c] = v;
    __nv_bfloat16 hi, lo; split32(v, hi, lo);
    Ahi[idx] = hi; Alo[idx] = lo;
    if (c < 36) GGt[(size_t)b * 36 + c] = 0.f;
}

__global__ void gather_result_kernel(const float* __restrict__ X, float* __restrict__ res, int up) {
    int idx = blockIdx.x * blockDim.x + threadIdx.x;
    if (idx >= BSZ * D) return;
    int b = idx >> 11;
    int c = idx & (D - 1);
    res[idx] = X[(size_t)b * LDF + up * D + c];
}

__global__ void trace_kernel(const double* __restrict__ norms,
                             float* __restrict__ rel, float* __restrict__ absd)
{
    int k = threadIdx.x;
    if (k < NITER) {
        double a = sqrt(norms[2 * k]);
        double fn = sqrt(norms[2 * k + 1]);
        absd[k] = (float)a;
        rel[k] = (float)(a / (1e-5 + fn));
    }
}

// ---------------- host ----------------
typedef CUresult (*PFN_tmEncode)(CUtensorMap*, CUtensorMapDataType, cuuint32_t, void*,
                                 const cuuint64_t*, const cuuint64_t*, const cuuint32_t*,
                                 const cuuint32_t*, CUtensorMapInterleave, CUtensorMapSwizzle,
                                 CUtensorMapL2promotion, CUtensorMapFloatOOBfill);

static void make_tm(PFN_tmEncode enc, CUtensorMap* tm, void* ptr, uint32_t box1) {
    cuuint64_t dims[2] = { (cuuint64_t)D, (cuuint64_t)D };
    cuuint64_t strides[1] = { (cuuint64_t)D * sizeof(__nv_bfloat16) };
    cuuint32_t box[2] = { TKt, box1 };
    cuuint32_t es[2] = { 1, 1 };
    enc(tm, CU_TENSOR_MAP_DATA_TYPE_BFLOAT16, 2, ptr, dims, strides, box, es,
        CU_TENSOR_MAP_INTERLEAVE_NONE, CU_TENSOR_MAP_SWIZZLE_128B,
        CU_TENSOR_MAP_L2_PROMOTION_L2_128B, CU_TENSOR_MAP_FLOAT_OOB_FILL_NONE);
}

extern "C" void kernel_launch(void* const* d_in, const int* in_sizes, int n_in,
                              void* d_out, int out_size)
{
    const float* x0   = (const float*)d_in[0];
    const float* W    = (const float*)d_in[1];
    const float* bias = (const float*)d_in[2];

    float* out = (float*)d_out;
    float* res  = out;
    float* X    = out + (size_t)BSZ * D;
    float* rel  = out + (size_t)BSZ * D + (size_t)BSZ * MM * D;
    float* absd = rel + NITER;

    float *Fp, *Gp, *alphap, *GGtp; __nv_bfloat16 *Ahip, *Alop, *Whip, *Wlop;
    double* normsp;
    cudaGetSymbolAddress((void**)&Fp, g_F);
    cudaGetSymbolAddress((void**)&Gp, g_G);
    cudaGetSymbolAddress((void**)&Ahip, g_Ahi);
    cudaGetSymbolAddress((void**)&Alop, g_Alo);
    cudaGetSymbolAddress((void**)&Whip, g_Whi);
    cudaGetSymbolAddress((void**)&Wlop, g_Wlo);
    cudaGetSymbolAddress((void**)&alphap, g_alpha);
    cudaGetSymbolAddress((void**)&GGtp, g_GGt);
    cudaGetSymbolAddress((void**)&normsp, g_norms);

    PFN_tmEncode enc = nullptr;
    {
        void* fp = nullptr;
        cudaDriverEntryPointQueryResult qr;
        cudaGetDriverEntryPoint("cuTensorMapEncodeTiled", &fp, cudaEnableDefault, &qr);
        enc = (PFN_tmEncode)fp;
    }
    CUtensorMap tmAhi, tmAlo, tmWhi, tmWlo;
    make_tm(enc, &tmAhi, Ahip, TMt);
    make_tm(enc, &tmAlo, Alop, TMt);
    make_tm(enc, &tmWhi, Whip, TNt);
    make_tm(enc, &tmWlo, Wlop, TNt);

    cudaFuncSetAttribute(mma_gemm_kernel, cudaFuncAttributeMaxDynamicSharedMemorySize, SMEM_TOTAL);

    zero_norms_kernel<<<1, 64>>>(normsp);

    {
        dim3 blk(32, 32), grd(D / 32, D / 32);
        wsplit_kernel<<<grd, blk>>>(W, Whip, Wlop);
    }

    // X[:,0]=x0, A=split(x0), GGt zeroed; then F/G slot 0 + Gram row 0
    scatter_x0_kernel<<<(BSZ * D + 255) / 256, 256>>>(x0, X, Ahip, Alop, GGtp);
    {
        dim3 grid(D / TNt, BSZ / TMt);
        mma_gemm_kernel<<<grid, 512, SMEM_TOTAL>>>(tmAhi, tmAlo, tmWhi, tmWlo, bias,
                                                   Fp, X, Gp, Gp, GGtp, 0, nullptr);
    }

    for (int k = 1; k < THRESH; k++) {
        int n = (k < MM) ? k : MM;
        int up = k % MM;

        solve_kernel<<<BSZ / 256, 256>>>(GGtp, alphap, n);
        {
            dim3 grid(2, BSZ);
            combine_kernel<<<grid, 256>>>(Fp, alphap, X, Ahip, Alop, GGtp, n, up);
        }
        {
            dim3 grid(D / TNt, BSZ / TMt);
            mma_gemm_kernel<<<grid, 512, SMEM_TOTAL>>>(tmAhi, tmAlo, tmWhi, tmWlo, bias,
                                                       Fp + up * D, X + up * D, Gp + up * D,
                                                       Gp, GGtp, up,
                                                       normsp + 2 * (k - 1));
        }
    }

    gather_result_kernel<<<(BSZ * D + 255) / 256, 256>>>(X, res, (THRESH - 1) % MM);
    trace_kernel<<<1, 32>>>(normsp, rel, absd);
}

// round 10
// speedup vs baseline: 1.0983x; 1.0983x over previous
#include <cuda_runtime.h>
#include <cuda.h>
#include <cuda_bf16.h>
#include <cstdint>

// Problem constants
#define BSZ   2048
#define D     2048
#define MM    6
#define THRESH 30
#define LAM   1.0e-4f
#define LDF   (MM*D)          // 12288
#define NITER (THRESH-1)      // 29

// GEMM tiling
#define TMt   128
#define TNt   256
#define TKt   64              // 64 bf16 = 128B rows, SW128
#define KITERS (D / TKt)      // 32
#define A_BYTES (TMt * TKt * 2)              // 16384
#define W_BYTES (TNt * TKt * 2)              // 32768
#define STAGE_BYTES (2*A_BYTES + 2*W_BYTES)  // 98304
#define SMEM_TOTAL (2*STAGE_BYTES + 2048)

// ---------------- device scratch ----------------
__device__ float         g_F[(size_t)BSZ * MM * D];
__device__ float         g_G[(size_t)BSZ * MM * D];   // G = F - X history
__device__ __nv_bfloat16 g_Ahi[(size_t)BSZ * D];
__device__ __nv_bfloat16 g_Alo[(size_t)BSZ * D];
__device__ __nv_bfloat16 g_Whi[(size_t)D * D];        // [N,K] transposed
__device__ __nv_bfloat16 g_Wlo[(size_t)D * D];
__device__ float         g_alpha[BSZ * 8];
__device__ float         g_GGt[BSZ * 36];
__device__ double        g_norms[2 * NITER + 2];

// ---------------- PTX helpers ----------------
__device__ __forceinline__ uint32_t smem_u32(const void* p) {
    uint32_t a;
    asm("{ .reg .u64 t; cvta.to.shared.u64 t, %1; cvt.u32.u64 %0, t; }" : "=r"(a) : "l"(p));
    return a;
}
#define MBAR_INIT(a, c) asm volatile("mbarrier.init.shared.b64 [%0], %1;" :: "r"(a), "r"(c) : "memory")
#define MBAR_EXPECT_TX(a, b) asm volatile("mbarrier.arrive.expect_tx.shared.b64 _, [%0], %1;" :: "r"(a), "r"(b) : "memory")
#define MBAR_ARRIVE(a) asm volatile("mbarrier.arrive.shared.b64 _, [%0];" :: "r"(a) : "memory")
#define MBAR_WAIT(a, ph) do { \
    uint32_t _m = (a); uint32_t _p = (ph); \
    asm volatile("{\n\t.reg .pred P1;\n\tWL_%=:\n\t" \
        "mbarrier.try_wait.parity.acquire.cta.shared::cta.b64 P1, [%0], %1, 0x989680;\n\t" \
        "@P1 bra.uni WD_%=;\n\tbra.uni WL_%=;\n\tWD_%=:\n\t}" \
        :: "r"(_m), "r"(_p) : "memory"); \
} while (0)

__device__ __forceinline__ void tma2d(uint32_t dst, const CUtensorMap* tm, int x, int y, uint32_t bar) {
    asm volatile(
        "cp.async.bulk.tensor.2d.shared::cta.global.tile.mbarrier::complete_tx::bytes "
        "[%0], [%1, {%2, %3}], [%4];"
        :: "r"(dst), "l"(tm), "r"(x), "r"(y), "r"(bar) : "memory");
}

#define LDSM4(r, addr) \
    asm volatile("ldmatrix.sync.aligned.m8n8.x4.shared.b16 {%0,%1,%2,%3}, [%4];" \
        : "=r"((r)[0]), "=r"((r)[1]), "=r"((r)[2]), "=r"((r)[3]) : "r"(addr))

#define MMA16816(d, a, b0, b1) \
    asm volatile("mma.sync.aligned.m16n8k16.row.col.f32.bf16.bf16.f32 " \
        "{%0,%1,%2,%3}, {%4,%5,%6,%7}, {%8,%9}, {%0,%1,%2,%3};" \
        : "+f"((d)[0]), "+f"((d)[1]), "+f"((d)[2]), "+f"((d)[3]) \
        : "r"((a)[0]), "r"((a)[1]), "r"((a)[2]), "r"((a)[3]), "r"(b0), "r"(b1))

__device__ __forceinline__ void split32(float v, __nv_bfloat16& hi, __nv_bfloat16& lo) {
    hi = __float2bfloat16(v);
    lo = __float2bfloat16(v - __bfloat162float(hi));
}

__device__ __forceinline__ float fast_tanh(float x) {
    float ax = fabsf(x);
    float e = __expf(2.0f * ax);
    float r = 1.0f - __fdividef(2.0f, e + 1.0f);
    return copysignf(r, x);
}

// ---------------- HMMA GEMM: F = tanh(A @ W^T + bias); G = F - X; norms ----------------
__global__ __launch_bounds__(512, 1)
void mma_gemm_kernel(const __grid_constant__ CUtensorMap tmAhi,
                     const __grid_constant__ CUtensorMap tmAlo,
                     const __grid_constant__ CUtensorMap tmWhi,
                     const __grid_constant__ CUtensorMap tmWlo,
                     const float* __restrict__ bias,
                     float* __restrict__ C,
                     const float* __restrict__ Xcur,
                     float* __restrict__ Gout,
                     double* norms_slot,
                     int ldc)
{
    extern __shared__ char smem[];
    __shared__ float red[2][16];
    const uint32_t sb = smem_u32(smem);
    const uint32_t stage0 = (sb + 1024 + 1023) & ~1023u;   // SW128 needs 1024-aligned tiles
    const int tid = threadIdx.x;
    const int lane = tid & 31;
    const int w = tid >> 5;
    const int wm = w & 3;
    const int wn = w >> 2;
    const int bm = blockIdx.y * TMt;
    const int bn = blockIdx.x * TNt;

    const uint32_t FULL[2]  = { sb,      sb + 8  };
    const uint32_t EMPTY[2] = { sb + 16, sb + 24 };

    if (tid == 0) {
        MBAR_INIT(FULL[0], 1);  MBAR_INIT(FULL[1], 1);
        MBAR_INIT(EMPTY[0], 16); MBAR_INIT(EMPTY[1], 16);
    }
    __syncthreads();

    if (tid == 0) {
        #pragma unroll
        for (int s = 0; s < 2; s++) {
            uint32_t st = stage0 + s * STAGE_BYTES;
            MBAR_EXPECT_TX(FULL[s], STAGE_BYTES);
            tma2d(st,                         &tmAhi, s * TKt, bm, FULL[s]);
            tma2d(st + A_BYTES,               &tmAlo, s * TKt, bm, FULL[s]);
            tma2d(st + 2 * A_BYTES,           &tmWhi, s * TKt, bn, FULL[s]);
            tma2d(st + 2 * A_BYTES + W_BYTES, &tmWlo, s * TKt, bn, FULL[s]);
        }
    }

    float acc[2][8][4];
    #pragma unroll
    for (int mt = 0; mt < 2; mt++)
        #pragma unroll
        for (int nt = 0; nt < 8; nt++)
            #pragma unroll
            for (int q = 0; q < 4; q++) acc[mt][nt][q] = 0.f;

    const uint32_t xorv = (uint32_t)(lane & 7) << 4;
    const uint32_t a_r = lane & 15;
    const uint32_t a_b = (uint32_t)(lane >> 4) << 4;
    const uint32_t b_r = ((uint32_t)(lane >> 4) << 3) + (lane & 7);
    const uint32_t b_b = (uint32_t)((lane >> 3) & 1) << 4;

    for (int i = 0; i < KITERS; i++) {
        const int buf = i & 1;
        const int ph = (i >> 1) & 1;
        MBAR_WAIT(FULL[buf], ph);

        const uint32_t st = stage0 + buf * STAGE_BYTES;
        const uint32_t Ahi_b = st;
        const uint32_t Alo_b = st + A_BYTES;
        const uint32_t Whi_b = st + 2 * A_BYTES;
        const uint32_t Wlo_b = st + 2 * A_BYTES + W_BYTES;

        #pragma unroll
        for (int k16 = 0; k16 < 4; k16++) {
            uint32_t ahi[2][4], alo[2][4];
            #pragma unroll
            for (int mt = 0; mt < 2; mt++) {
                uint32_t R = wm * 32 + mt * 16 + a_r;
                uint32_t B = a_b + k16 * 32;
                uint32_t off = R * 128 + (B ^ xorv);
                LDSM4(ahi[mt], Ahi_b + off);
                LDSM4(alo[mt], Alo_b + off);
            }
            #pragma unroll
            for (int p = 0; p < 4; p++) {
                uint32_t R = wn * 64 + p * 16 + b_r;
                uint32_t B = b_b + k16 * 32;
                uint32_t off = R * 128 + (B ^ xorv);
                uint32_t wh[4], wl[4];
                LDSM4(wh, Whi_b + off);
                LDSM4(wl, Wlo_b + off);
                #pragma unroll
                for (int mt = 0; mt < 2; mt++) {
                    #pragma unroll
                    for (int q = 0; q < 2; q++) {
                        float* d = acc[mt][2 * p + q];
                        MMA16816(d, ahi[mt], wh[2 * q], wh[2 * q + 1]);
                        MMA16816(d, ahi[mt], wl[2 * q], wl[2 * q + 1]);
                        MMA16816(d, alo[mt], wh[2 * q], wh[2 * q + 1]);
                    }
                }
            }
        }
        if (lane == 0) MBAR_ARRIVE(EMPTY[buf]);
        if (tid == 0 && i + 2 < KITERS) {
            MBAR_WAIT(EMPTY[buf], ph);
            MBAR_EXPECT_TX(FULL[buf], STAGE_BYTES);
            int k0 = (i + 2) * TKt;
            tma2d(st,                         &tmAhi, k0, bm, FULL[buf]);
            tma2d(st + A_BYTES,               &tmAlo, k0, bm, FULL[buf]);
            tma2d(st + 2 * A_BYTES,           &tmWhi, k0, bn, FULL[buf]);
            tma2d(st + 2 * A_BYTES + W_BYTES, &tmWlo, k0, bn, FULL[buf]);
        }
    }

    // epilogue: bias + tanh -> F; g = f - x -> G; accumulate norms
    const int r_in = lane >> 2;
    const int c_in = (lane & 3) * 2;
    float sg = 0.f, sf = 0.f;
    #pragma unroll
    for (int mt = 0; mt < 2; mt++) {
        const int row = bm + wm * 32 + mt * 16 + r_in;
        #pragma unroll
        for (int nt = 0; nt < 8; nt++) {
            const int col = bn + wn * 64 + nt * 8 + c_in;
            float2 bb = *(const float2*)(bias + col);
            float v0 = fast_tanh(acc[mt][nt][0] + bb.x);
            float v1 = fast_tanh(acc[mt][nt][1] + bb.y);
            float v2 = fast_tanh(acc[mt][nt][2] + bb.x);
            float v3 = fast_tanh(acc[mt][nt][3] + bb.y);
            size_t o0 = (size_t)row * ldc + col;
            size_t o1 = (size_t)(row + 8) * ldc + col;
            float2 x0 = *(const float2*)(Xcur + o0);
            float2 x1 = *(const float2*)(Xcur + o1);
            float g0 = v0 - x0.x, g1 = v1 - x0.y;
            float g2 = v2 - x1.x, g3 = v3 - x1.y;
            *(float2*)(C + o0) = make_float2(v0, v1);
            *(float2*)(C + o1) = make_float2(v2, v3);
            *(float2*)(Gout + o0) = make_float2(g0, g1);
            *(float2*)(Gout + o1) = make_float2(g2, g3);
            sg += g0 * g0 + g1 * g1 + g2 * g2 + g3 * g3;
            sf += v0 * v0 + v1 * v1 + v2 * v2 + v3 * v3;
        }
    }
    if (norms_slot != nullptr) {
        #pragma unroll
        for (int s = 16; s > 0; s >>= 1) {
            sg += __shfl_xor_sync(0xFFFFFFFF, sg, s);
            sf += __shfl_xor_sync(0xFFFFFFFF, sf, s);
        }
        if (lane == 0) { red[0][w] = sg; red[1][w] = sf; }
        __syncthreads();
        if (w == 0 && lane < 16) {
            float a = red[0][lane], b = red[1][lane];
            #pragma unroll
            for (int s = 8; s > 0; s >>= 1) {
                a += __shfl_xor_sync(0xFFFF, a, s);
                b += __shfl_xor_sync(0xFFFF, b, s);
            }
            if (lane == 0) {
                atomicAdd(&norms_slot[0], (double)a);
                atomicAdd(&norms_slot[1], (double)b);
            }
        }
    }
}

// ---------------- batched Gram from G (float4) ----------------
__global__ __launch_bounds__(256)
void gram_kernel(const float* __restrict__ G, float* __restrict__ GGt, int n)
{
    int b = blockIdx.x;
    const float4* Gb = (const float4*)(G + (size_t)b * LDF);

    float acc[21];
#pragma unroll
    for (int p = 0; p < 21; p++) acc[p] = 0.f;

#pragma unroll
    for (int rep = 0; rep < 2; rep++) {
        int c4 = threadIdx.x + rep * 256;   // 0..511
        float4 g4[6];
#pragma unroll
        for (int j = 0; j < 6; j++) {
            if (j < n) g4[j] = Gb[j * 512 + c4];
            else g4[j] = make_float4(0.f, 0.f, 0.f, 0.f);
        }
        int p = 0;
#pragma unroll
        for (int i = 0; i < 6; i++)
#pragma unroll
            for (int j = i; j < 6; j++) {
                acc[p] += g4[i].x * g4[j].x + g4[i].y * g4[j].y
                        + g4[i].z * g4[j].z + g4[i].w * g4[j].w;
                p++;
            }
    }

    __shared__ float sm[256][21];
#pragma unroll
    for (int p = 0; p < 21; p++) sm[threadIdx.x][p] = acc[p];
    __syncthreads();
    for (int s = 128; s > 0; s >>= 1) {
        if (threadIdx.x < s) {
#pragma unroll
            for (int p = 0; p < 21; p++) sm[threadIdx.x][p] += sm[threadIdx.x + s][p];
        }
        __syncthreads();
    }
    if (threadIdx.x == 0) {
        float* out = GGt + (size_t)b * 36;
        int p = 0;
        for (int i = 0; i < 6; i++)
            for (int j = i; j < 6; j++) {
                float v = sm[0][p++];
                if (i == j) v += LAM;
                out[i * 6 + j] = v;
                out[j * 6 + i] = v;
            }
    }
}

// ---------------- bordered solve (one batch per thread) ----------------
__global__ void solve_kernel(const float* __restrict__ GGt, float* __restrict__ alpha, int n)
{
    int b = blockIdx.x * blockDim.x + threadIdx.x;
    if (b >= BSZ) return;
    const int s = n + 1;
    float H[7][7];
    float y[7];
    H[0][0] = 0.f; y[0] = 1.f;
    for (int i = 1; i < s; i++) { H[0][i] = 1.f; H[i][0] = 1.f; y[i] = 0.f; }
    const float* G = GGt + (size_t)b * 36;
    for (int i = 0; i < n; i++)
        for (int j = 0; j < n; j++)
            H[i + 1][j + 1] = G[i * 6 + j];

    for (int c = 0; c < s; c++) {
        int piv = c;
        float mx = fabsf(H[c][c]);
        for (int r = c + 1; r < s; r++) {
            float v = fabsf(H[r][c]);
            if (v > mx) { mx = v; piv = r; }
        }
        if (piv != c) {
            for (int cc = 0; cc < s; cc++) { float t = H[c][cc]; H[c][cc] = H[piv][cc]; H[piv][cc] = t; }
            float t = y[c]; y[c] = y[piv]; y[piv] = t;
        }
        float inv = 1.f / H[c][c];
        for (int r = c + 1; r < s; r++) {
            float f = H[r][c] * inv;
            if (f != 0.f) {
                for (int cc = c; cc < s; cc++) H[r][cc] -= f * H[c][cc];
                y[r] -= f * y[c];
            }
        }
    }
    float sol[7];
    for (int r = s - 1; r >= 0; r--) {
        float a = y[r];
        for (int cc = r + 1; cc < s; cc++) a -= H[r][cc] * sol[cc];
        sol[r] = a / H[r][r];
    }
    float* ab = alpha + b * 8;
    for (int i = 0; i < 6; i++) ab[i] = (i < n) ? sol[i + 1] : 0.f;
}

// ---------------- combine (float4) + bf16 split of xnew (+ optional result write) ----------------
__global__ __launch_bounds__(256)
void combine_kernel(const float* __restrict__ F, const float* __restrict__ alpha,
                    float* __restrict__ X,
                    __nv_bfloat16* __restrict__ Ahi, __nv_bfloat16* __restrict__ Alo,
                    float* __restrict__ res,    // may be null; written on last iteration
                    int n, int up)
{
    int b = blockIdx.y;
    int c4 = blockIdx.x * 256 + threadIdx.x;
    const float4* Fb = (const float4*)(F + (size_t)b * LDF);
    const float* ab = alpha + b * 8;
    float4 acc = make_float4(0.f, 0.f, 0.f, 0.f);
#pragma unroll
    for (int j = 0; j < 6; j++) {
        if (j < n) {
            float a = ab[j];
            float4 f = Fb[j * 512 + c4];
            acc.x += a * f.x; acc.y += a * f.y; acc.z += a * f.z; acc.w += a * f.w;
        }
    }
    ((float4*)(X + (size_t)b * LDF + up * D))[c4] = acc;
    if (res != nullptr)
        ((float4*)(res + (size_t)b * D))[c4] = acc;

    __nv_bfloat16 h0, l0, h1, l1, h2, l2, h3, l3;
    split32(acc.x, h0, l0); split32(acc.y, h1, l1);
    split32(acc.z, h2, l2); split32(acc.w, h3, l3);
    __nv_bfloat162* Ah = (__nv_bfloat162*)(Ahi + (size_t)b * D);
    __nv_bfloat162* Al = (__nv_bfloat162*)(Alo + (size_t)b * D);
    Ah[c4 * 2]     = __nv_bfloat162(h0, h1);
    Ah[c4 * 2 + 1] = __nv_bfloat162(h2, h3);
    Al[c4 * 2]     = __nv_bfloat162(l0, l1);
    Al[c4 * 2 + 1] = __nv_bfloat162(l2, l3);
}

// ---------------- W transpose + bf16 split ----------------
__global__ __launch_bounds__(1024)
void wsplit_kernel(const float* __restrict__ W,
                   __nv_bfloat16* __restrict__ Whi, __nv_bfloat16* __restrict__ Wlo)
{
    __shared__ float t[32][33];
    int n0 = blockIdx.x * 32, k0 = blockIdx.y * 32;
    t[threadIdx.y][threadIdx.x] = W[(size_t)(k0 + threadIdx.y) * D + n0 + threadIdx.x];
    __syncthreads();
    float v = t[threadIdx.x][threadIdx.y];
    __nv_bfloat16 hi, lo; split32(v, hi, lo);
    size_t o = (size_t)(n0 + threadIdx.y) * D + k0 + threadIdx.x;
    Whi[o] = hi; Wlo[o] = lo;
}

// ---------------- small utility kernels ----------------
__global__ void zero_norms_kernel(double* norms) {
    int i = threadIdx.x;
    if (i < 2 * NITER + 2) norms[i] = 0.0;
}

__global__ void scatter_x0_kernel(const float* __restrict__ x0, float* __restrict__ X,
                                  __nv_bfloat16* __restrict__ Ahi, __nv_bfloat16* __restrict__ Alo) {
    int idx = blockIdx.x * blockDim.x + threadIdx.x;
    if (idx >= BSZ * D) return;
    int b = idx >> 11;
    int c = idx & (D - 1);
    float v = x0[idx];
    X[(size_t)b * LDF + c] = v;
    __nv_bfloat16 hi, lo; split32(v, hi, lo);
    Ahi[idx] = hi; Alo[idx] = lo;
}

__global__ void trace_kernel(const double* __restrict__ norms,
                             float* __restrict__ rel, float* __restrict__ absd)
{
    int k = threadIdx.x;
    if (k < NITER) {
        double a = sqrt(norms[2 * k]);
        double fn = sqrt(norms[2 * k + 1]);
        absd[k] = (float)a;
        rel[k] = (float)(a / (1e-5 + fn));
    }
}

// ---------------- host ----------------
typedef CUresult (*PFN_tmEncode)(CUtensorMap*, CUtensorMapDataType, cuuint32_t, void*,
                                 const cuuint64_t*, const cuuint64_t*, const cuuint32_t*,
                                 const cuuint32_t*, CUtensorMapInterleave, CUtensorMapSwizzle,
                                 CUtensorMapL2promotion, CUtensorMapFloatOOBfill);

static void make_tm(PFN_tmEncode enc, CUtensorMap* tm, void* ptr, uint32_t box1) {
    cuuint64_t dims[2] = { (cuuint64_t)D, (cuuint64_t)D };
    cuuint64_t strides[1] = { (cuuint64_t)D * sizeof(__nv_bfloat16) };
    cuuint32_t box[2] = { TKt, box1 };
    cuuint32_t es[2] = { 1, 1 };
    enc(tm, CU_TENSOR_MAP_DATA_TYPE_BFLOAT16, 2, ptr, dims, strides, box, es,
        CU_TENSOR_MAP_INTERLEAVE_NONE, CU_TENSOR_MAP_SWIZZLE_128B,
        CU_TENSOR_MAP_L2_PROMOTION_L2_128B, CU_TENSOR_MAP_FLOAT_OOB_FILL_NONE);
}

extern "C" void kernel_launch(void* const* d_in, const int* in_sizes, int n_in,
                              void* d_out, int out_size)
{
    const float* x0   = (const float*)d_in[0];
    const float* W    = (const float*)d_in[1];
    const float* bias = (const float*)d_in[2];

    float* out = (float*)d_out;
    float* res  = out;
    float* X    = out + (size_t)BSZ * D;
    float* rel  = out + (size_t)BSZ * D + (size_t)BSZ * MM * D;
    float* absd = rel + NITER;

    float *Fp, *Gp, *alphap, *GGtp; __nv_bfloat16 *Ahip, *Alop, *Whip, *Wlop;
    double* normsp;
    cudaGetSymbolAddress((void**)&Fp, g_F);
    cudaGetSymbolAddress((void**)&Gp, g_G);
    cudaGetSymbolAddress((void**)&Ahip, g_Ahi);
    cudaGetSymbolAddress((void**)&Alop, g_Alo);
    cudaGetSymbolAddress((void**)&Whip, g_Whi);
    cudaGetSymbolAddress((void**)&Wlop, g_Wlo);
    cudaGetSymbolAddress((void**)&alphap, g_alpha);
    cudaGetSymbolAddress((void**)&GGtp, g_GGt);
    cudaGetSymbolAddress((void**)&normsp, g_norms);

    PFN_tmEncode enc = nullptr;
    {
        void* fp = nullptr;
        cudaDriverEntryPointQueryResult qr;
        cudaGetDriverEntryPoint("cuTensorMapEncodeTiled", &fp, cudaEnableDefault, &qr);
        enc = (PFN_tmEncode)fp;
    }
    CUtensorMap tmAhi, tmAlo, tmWhi, tmWlo;
    make_tm(enc, &tmAhi, Ahip, TMt);
    make_tm(enc, &tmAlo, Alop, TMt);
    make_tm(enc, &tmWhi, Whip, TNt);
    make_tm(enc, &tmWlo, Wlop, TNt);

    cudaFuncSetAttribute(mma_gemm_kernel, cudaFuncAttributeMaxDynamicSharedMemorySize, SMEM_TOTAL);

    zero_norms_kernel<<<1, 64>>>(normsp);

    {
        dim3 blk(32, 32), grd(D / 32, D / 32);
        wsplit_kernel<<<grd, blk>>>(W, Whip, Wlop);
    }

    scatter_x0_kernel<<<(BSZ * D + 255) / 256, 256>>>(x0, X, Ahip, Alop);
    {
        dim3 grid(D / TNt, BSZ / TMt);
        mma_gemm_kernel<<<grid, 512, SMEM_TOTAL>>>(tmAhi, tmAlo, tmWhi, tmWlo, bias,
                                                   Fp, X, Gp, nullptr, LDF);
    }

    for (int k = 1; k < THRESH; k++) {
        int n = (k < MM) ? k : MM;
        int up = k % MM;

        gram_kernel<<<BSZ, 256>>>(Gp, GGtp, n);
        solve_kernel<<<BSZ / 256, 256>>>(GGtp, alphap, n);
        {
            dim3 grid(2, BSZ);
            combine_kernel<<<grid, 256>>>(Fp, alphap, X, Ahip, Alop,
                                          (k == THRESH - 1) ? res : nullptr, n, up);
        }
        {
            dim3 grid(D / TNt, BSZ / TMt);
            mma_gemm_kernel<<<grid, 512, SMEM_TOTAL>>>(tmAhi, tmAlo, tmWhi, tmWlo, bias,
                                                       Fp + up * D, X + up * D, Gp + up * D,
                                                       normsp + 2 * (k - 1), LDF);
        }
    }

    trace_kernel<<<1, 32>>>(normsp, rel, absd);
}

// round 11
// speedup vs baseline: 1.1809x; 1.0752x over previous
#include <cuda_runtime.h>
#include <cuda.h>
#include <cuda_bf16.h>
#include <cstdint>

// Problem constants
#define BSZ   2048
#define D     2048
#define MM    6
#define THRESH 30
#define LAM   1.0e-4f
#define LDF   (MM*D)          // 12288
#define NITER (THRESH-1)      // 29

// GEMM tiling
#define TMt   128
#define TNt   256
#define TKt   64              // 64 bf16 = 128B rows, SW128
#define KITERS (D / TKt)      // 32
#define A_BYTES (TMt * TKt * 2)              // 16384
#define W_BYTES (TNt * TKt * 2)              // 32768
#define STAGE_BYTES (2*A_BYTES + 2*W_BYTES)  // 98304
#define SMEM_TOTAL (2*STAGE_BYTES + 2048)

// ---------------- device scratch ----------------
__device__ float         g_F[(size_t)BSZ * MM * D];
__device__ float         g_G[(size_t)BSZ * MM * D];   // G = F - X history
__device__ __nv_bfloat16 g_Ahi[(size_t)BSZ * D];
__device__ __nv_bfloat16 g_Alo[(size_t)BSZ * D];
__device__ __nv_bfloat16 g_Whi[(size_t)D * D];        // [N,K] transposed
__device__ __nv_bfloat16 g_Wlo[(size_t)D * D];
__device__ float         g_alpha[BSZ * 8];
__device__ double        g_norms[2 * NITER + 2];

// ---------------- PTX helpers ----------------
__device__ __forceinline__ uint32_t smem_u32(const void* p) {
    uint32_t a;
    asm("{ .reg .u64 t; cvta.to.shared.u64 t, %1; cvt.u32.u64 %0, t; }" : "=r"(a) : "l"(p));
    return a;
}
#define MBAR_INIT(a, c) asm volatile("mbarrier.init.shared.b64 [%0], %1;" :: "r"(a), "r"(c) : "memory")
#define MBAR_EXPECT_TX(a, b) asm volatile("mbarrier.arrive.expect_tx.shared.b64 _, [%0], %1;" :: "r"(a), "r"(b) : "memory")
#define MBAR_ARRIVE(a) asm volatile("mbarrier.arrive.shared.b64 _, [%0];" :: "r"(a) : "memory")
#define MBAR_WAIT(a, ph) do { \
    uint32_t _m = (a); uint32_t _p = (ph); \
    asm volatile("{\n\t.reg .pred P1;\n\tWL_%=:\n\t" \
        "mbarrier.try_wait.parity.acquire.cta.shared::cta.b64 P1, [%0], %1, 0x989680;\n\t" \
        "@P1 bra.uni WD_%=;\n\tbra.uni WL_%=;\n\tWD_%=:\n\t}" \
        :: "r"(_m), "r"(_p) : "memory"); \
} while (0)

__device__ __forceinline__ void tma2d(uint32_t dst, const CUtensorMap* tm, int x, int y, uint32_t bar) {
    asm volatile(
        "cp.async.bulk.tensor.2d.shared::cta.global.tile.mbarrier::complete_tx::bytes "
        "[%0], [%1, {%2, %3}], [%4];"
        :: "r"(dst), "l"(tm), "r"(x), "r"(y), "r"(bar) : "memory");
}

#define LDSM4(r, addr) \
    asm volatile("ldmatrix.sync.aligned.m8n8.x4.shared.b16 {%0,%1,%2,%3}, [%4];" \
        : "=r"((r)[0]), "=r"((r)[1]), "=r"((r)[2]), "=r"((r)[3]) : "r"(addr))

#define MMA16816(d, a, b0, b1) \
    asm volatile("mma.sync.aligned.m16n8k16.row.col.f32.bf16.bf16.f32 " \
        "{%0,%1,%2,%3}, {%4,%5,%6,%7}, {%8,%9}, {%0,%1,%2,%3};" \
        : "+f"((d)[0]), "+f"((d)[1]), "+f"((d)[2]), "+f"((d)[3]) \
        : "r"((a)[0]), "r"((a)[1]), "r"((a)[2]), "r"((a)[3]), "r"(b0), "r"(b1))

__device__ __forceinline__ void split32(float v, __nv_bfloat16& hi, __nv_bfloat16& lo) {
    hi = __float2bfloat16(v);
    lo = __float2bfloat16(v - __bfloat162float(hi));
}

__device__ __forceinline__ float fast_tanh(float x) {
    float ax = fabsf(x);
    float e = __expf(2.0f * ax);
    float r = 1.0f - __fdividef(2.0f, e + 1.0f);
    return copysignf(r, x);
}

// ---------------- HMMA GEMM: F = tanh(A @ W^T + bias); G = F - X; norms ----------------
__global__ __launch_bounds__(512, 1)
void mma_gemm_kernel(const __grid_constant__ CUtensorMap tmAhi,
                     const __grid_constant__ CUtensorMap tmAlo,
                     const __grid_constant__ CUtensorMap tmWhi,
                     const __grid_constant__ CUtensorMap tmWlo,
                     const float* __restrict__ bias,
                     float* __restrict__ C,
                     const float* __restrict__ Xcur,
                     float* __restrict__ Gout,
                     double* norms_slot,
                     int ldc)
{
    extern __shared__ char smem[];
    __shared__ float red[2][16];
    const uint32_t sb = smem_u32(smem);
    const uint32_t stage0 = (sb + 1024 + 1023) & ~1023u;   // SW128 needs 1024-aligned tiles
    const int tid = threadIdx.x;
    const int lane = tid & 31;
    const int w = tid >> 5;
    const int wm = w & 3;
    const int wn = w >> 2;
    const int bm = blockIdx.y * TMt;
    const int bn = blockIdx.x * TNt;

    const uint32_t FULL[2]  = { sb,      sb + 8  };
    const uint32_t EMPTY[2] = { sb + 16, sb + 24 };

    if (tid == 0) {
        MBAR_INIT(FULL[0], 1);  MBAR_INIT(FULL[1], 1);
        MBAR_INIT(EMPTY[0], 16); MBAR_INIT(EMPTY[1], 16);
    }
    __syncthreads();

    if (tid == 0) {
        #pragma unroll
        for (int s = 0; s < 2; s++) {
            uint32_t st = stage0 + s * STAGE_BYTES;
            MBAR_EXPECT_TX(FULL[s], STAGE_BYTES);
            tma2d(st,                         &tmAhi, s * TKt, bm, FULL[s]);
            tma2d(st + A_BYTES,               &tmAlo, s * TKt, bm, FULL[s]);
            tma2d(st + 2 * A_BYTES,           &tmWhi, s * TKt, bn, FULL[s]);
            tma2d(st + 2 * A_BYTES + W_BYTES, &tmWlo, s * TKt, bn, FULL[s]);
        }
    }

    float acc[2][8][4];
    #pragma unroll
    for (int mt = 0; mt < 2; mt++)
        #pragma unroll
        for (int nt = 0; nt < 8; nt++)
            #pragma unroll
            for (int q = 0; q < 4; q++) acc[mt][nt][q] = 0.f;

    const uint32_t xorv = (uint32_t)(lane & 7) << 4;
    const uint32_t a_r = lane & 15;
    const uint32_t a_b = (uint32_t)(lane >> 4) << 4;
    const uint32_t b_r = ((uint32_t)(lane >> 4) << 3) + (lane & 7);
    const uint32_t b_b = (uint32_t)((lane >> 3) & 1) << 4;

    for (int i = 0; i < KITERS; i++) {
        const int buf = i & 1;
        const int ph = (i >> 1) & 1;
        MBAR_WAIT(FULL[buf], ph);

        const uint32_t st = stage0 + buf * STAGE_BYTES;
        const uint32_t Ahi_b = st;
        const uint32_t Alo_b = st + A_BYTES;
        const uint32_t Whi_b = st + 2 * A_BYTES;
        const uint32_t Wlo_b = st + 2 * A_BYTES + W_BYTES;

        #pragma unroll
        for (int k16 = 0; k16 < 4; k16++) {
            uint32_t ahi[2][4], alo[2][4];
            #pragma unroll
            for (int mt = 0; mt < 2; mt++) {
                uint32_t R = wm * 32 + mt * 16 + a_r;
                uint32_t B = a_b + k16 * 32;
                uint32_t off = R * 128 + (B ^ xorv);
                LDSM4(ahi[mt], Ahi_b + off);
                LDSM4(alo[mt], Alo_b + off);
            }
            #pragma unroll
            for (int p = 0; p < 4; p++) {
                uint32_t R = wn * 64 + p * 16 + b_r;
                uint32_t B = b_b + k16 * 32;
                uint32_t off = R * 128 + (B ^ xorv);
                uint32_t wh[4], wl[4];
                LDSM4(wh, Whi_b + off);
                LDSM4(wl, Wlo_b + off);
                #pragma unroll
                for (int mt = 0; mt < 2; mt++) {
                    #pragma unroll
                    for (int q = 0; q < 2; q++) {
                        float* d = acc[mt][2 * p + q];
                        MMA16816(d, ahi[mt], wh[2 * q], wh[2 * q + 1]);
                        MMA16816(d, ahi[mt], wl[2 * q], wl[2 * q + 1]);
                        MMA16816(d, alo[mt], wh[2 * q], wh[2 * q + 1]);
                    }
                }
            }
        }
        if (lane == 0) MBAR_ARRIVE(EMPTY[buf]);
        if (tid == 0 && i + 2 < KITERS) {
            MBAR_WAIT(EMPTY[buf], ph);
            MBAR_EXPECT_TX(FULL[buf], STAGE_BYTES);
            int k0 = (i + 2) * TKt;
            tma2d(st,                         &tmAhi, k0, bm, FULL[buf]);
            tma2d(st + A_BYTES,               &tmAlo, k0, bm, FULL[buf]);
            tma2d(st + 2 * A_BYTES,           &tmWhi, k0, bn, FULL[buf]);
            tma2d(st + 2 * A_BYTES + W_BYTES, &tmWlo, k0, bn, FULL[buf]);
        }
    }

    // epilogue: bias + tanh -> F; g = f - x -> G; accumulate norms
    const int r_in = lane >> 2;
    const int c_in = (lane & 3) * 2;
    float sg = 0.f, sf = 0.f;
    #pragma unroll
    for (int mt = 0; mt < 2; mt++) {
        const int row = bm + wm * 32 + mt * 16 + r_in;
        #pragma unroll
        for (int nt = 0; nt < 8; nt++) {
            const int col = bn + wn * 64 + nt * 8 + c_in;
            float2 bb = *(const float2*)(bias + col);
            float v0 = fast_tanh(acc[mt][nt][0] + bb.x);
            float v1 = fast_tanh(acc[mt][nt][1] + bb.y);
            float v2 = fast_tanh(acc[mt][nt][2] + bb.x);
            float v3 = fast_tanh(acc[mt][nt][3] + bb.y);
            size_t o0 = (size_t)row * ldc + col;
            size_t o1 = (size_t)(row + 8) * ldc + col;
            float2 x0 = *(const float2*)(Xcur + o0);
            float2 x1 = *(const float2*)(Xcur + o1);
            float g0 = v0 - x0.x, g1 = v1 - x0.y;
            float g2 = v2 - x1.x, g3 = v3 - x1.y;
            *(float2*)(C + o0) = make_float2(v0, v1);
            *(float2*)(C + o1) = make_float2(v2, v3);
            *(float2*)(Gout + o0) = make_float2(g0, g1);
            *(float2*)(Gout + o1) = make_float2(g2, g3);
            sg += g0 * g0 + g1 * g1 + g2 * g2 + g3 * g3;
            sf += v0 * v0 + v1 * v1 + v2 * v2 + v3 * v3;
        }
    }
    if (norms_slot != nullptr) {
        #pragma unroll
        for (int s = 16; s > 0; s >>= 1) {
            sg += __shfl_xor_sync(0xFFFFFFFF, sg, s);
            sf += __shfl_xor_sync(0xFFFFFFFF, sf, s);
        }
        if (lane == 0) { red[0][w] = sg; red[1][w] = sf; }
        __syncthreads();
        if (w == 0 && lane < 16) {
            float a = red[0][lane], b = red[1][lane];
            #pragma unroll
            for (int s = 8; s > 0; s >>= 1) {
                a += __shfl_xor_sync(0xFFFF, a, s);
                b += __shfl_xor_sync(0xFFFF, b, s);
            }
            if (lane == 0) {
                atomicAdd(&norms_slot[0], (double)a);
                atomicAdd(&norms_slot[1], (double)b);
            }
        }
    }
}

// ---------------- Gram (float4) + register-Cholesky solve -> alpha ----------------
// alpha = A^{-1} 1 / (1^T A^{-1} 1), A = GGt + lam I  (SPD, pivot-free, static indices)
__global__ __launch_bounds__(256)
void gram_solve_kernel(const float* __restrict__ G, float* __restrict__ alpha, int n)
{
    int b = blockIdx.x;
    const float4* Gb = (const float4*)(G + (size_t)b * LDF);

    float acc[21];
#pragma unroll
    for (int p = 0; p < 21; p++) acc[p] = 0.f;

#pragma unroll
    for (int rep = 0; rep < 2; rep++) {
        int c4 = threadIdx.x + rep * 256;   // 0..511
        float4 g4[6];
#pragma unroll
        for (int j = 0; j < 6; j++) {
            if (j < n) g4[j] = Gb[j * 512 + c4];
            else g4[j] = make_float4(0.f, 0.f, 0.f, 0.f);
        }
        int p = 0;
#pragma unroll
        for (int i = 0; i < 6; i++)
#pragma unroll
            for (int j = i; j < 6; j++) {
                acc[p] += g4[i].x * g4[j].x + g4[i].y * g4[j].y
                        + g4[i].z * g4[j].z + g4[i].w * g4[j].w;
                p++;
            }
    }

    __shared__ float sm[256][21];
#pragma unroll
    for (int p = 0; p < 21; p++) sm[threadIdx.x][p] = acc[p];
    __syncthreads();
    for (int s = 128; s > 0; s >>= 1) {
        if (threadIdx.x < s) {
#pragma unroll
            for (int p = 0; p < 21; p++) sm[threadIdx.x][p] += sm[threadIdx.x + s][p];
        }
        __syncthreads();
    }

    // All threads redundantly solve (uniform data, static indexing -> registers).
    {
        float A[6][6];
        int p = 0;
#pragma unroll
        for (int i = 0; i < 6; i++)
#pragma unroll
            for (int j = i; j < 6; j++) {
                float v = sm[0][p++];
                if (i == j) v += LAM;
                A[i][j] = v; A[j][i] = v;
            }
        // Cholesky (lower, in place), guarded by runtime n with static indices
#pragma unroll
        for (int c = 0; c < 6; c++) {
            if (c < n) {
                float d = A[c][c];
#pragma unroll
                for (int m = 0; m < 6; m++) if (m < c) d -= A[c][m] * A[c][m];
                d = fmaxf(d, 1e-12f);
                float lcc = sqrtf(d);
                A[c][c] = lcc;
                float inv = __fdividef(1.f, lcc);
#pragma unroll
                for (int r = 0; r < 6; r++) {
                    if (r > c && r < n) {
                        float sdot = A[r][c];
#pragma unroll
                        for (int m = 0; m < 6; m++) if (m < c) sdot -= A[r][m] * A[c][m];
                        A[r][c] = sdot * inv;
                    }
                }
            }
        }
        // L y = 1
        float y[6];
#pragma unroll
        for (int c = 0; c < 6; c++) {
            float v = 1.f;
#pragma unroll
            for (int m = 0; m < 6; m++) if (m < c) v -= A[c][m] * y[m];
            y[c] = (c < n) ? __fdividef(v, A[c][c]) : 0.f;
        }
        // L^T z = y
        float z[6];
#pragma unroll
        for (int c = 5; c >= 0; c--) {
            float v = y[c];
#pragma unroll
            for (int m = 0; m < 6; m++) if (m > c) v -= A[m][c] * z[m];
            z[c] = (c < n) ? __fdividef(v, A[c][c]) : 0.f;
        }
        float ssum = z[0] + z[1] + z[2] + z[3] + z[4] + z[5];
        float invs = __fdividef(1.f, ssum);
        if (threadIdx.x == 0) {
            float* ab = alpha + b * 8;
#pragma unroll
            for (int j = 0; j < 6; j++) ab[j] = z[j] * invs;
        }
    }
}

// ---------------- combine (float4) + bf16 split of xnew (+ optional result write) ----------------
__global__ __launch_bounds__(256)
void combine_kernel(const float* __restrict__ F, const float* __restrict__ alpha,
                    float* __restrict__ X,
                    __nv_bfloat16* __restrict__ Ahi, __nv_bfloat16* __restrict__ Alo,
                    float* __restrict__ res,    // may be null; written on last iteration
                    int n, int up)
{
    int b = blockIdx.y;
    int c4 = blockIdx.x * 256 + threadIdx.x;
    const float4* Fb = (const float4*)(F + (size_t)b * LDF);
    const float* ab = alpha + b * 8;
    float4 acc = make_float4(0.f, 0.f, 0.f, 0.f);
#pragma unroll
    for (int j = 0; j < 6; j++) {
        if (j < n) {
            float a = ab[j];
            float4 f = Fb[j * 512 + c4];
            acc.x += a * f.x; acc.y += a * f.y; acc.z += a * f.z; acc.w += a * f.w;
        }
    }
    ((float4*)(X + (size_t)b * LDF + up * D))[c4] = acc;
    if (res != nullptr)
        ((float4*)(res + (size_t)b * D))[c4] = acc;

    __nv_bfloat16 h0, l0, h1, l1, h2, l2, h3, l3;
    split32(acc.x, h0, l0); split32(acc.y, h1, l1);
    split32(acc.z, h2, l2); split32(acc.w, h3, l3);
    __nv_bfloat162* Ah = (__nv_bfloat162*)(Ahi + (size_t)b * D);
    __nv_bfloat162* Al = (__nv_bfloat162*)(Alo + (size_t)b * D);
    Ah[c4 * 2]     = __nv_bfloat162(h0, h1);
    Ah[c4 * 2 + 1] = __nv_bfloat162(h2, h3);
    Al[c4 * 2]     = __nv_bfloat162(l0, l1);
    Al[c4 * 2 + 1] = __nv_bfloat162(l2, l3);
}

// ---------------- W transpose + bf16 split ----------------
__global__ __launch_bounds__(1024)
void wsplit_kernel(const float* __restrict__ W,
                   __nv_bfloat16* __restrict__ Whi, __nv_bfloat16* __restrict__ Wlo)
{
    __shared__ float t[32][33];
    int n0 = blockIdx.x * 32, k0 = blockIdx.y * 32;
    t[threadIdx.y][threadIdx.x] = W[(size_t)(k0 + threadIdx.y) * D + n0 + threadIdx.x];
    __syncthreads();
    float v = t[threadIdx.x][threadIdx.y];
    __nv_bfloat16 hi, lo; split32(v, hi, lo);
    size_t o = (size_t)(n0 + threadIdx.y) * D + k0 + threadIdx.x;
    Whi[o] = hi; Wlo[o] = lo;
}

// ---------------- small utility kernels ----------------
__global__ void zero_norms_kernel(double* norms) {
    int i = threadIdx.x;
    if (i < 2 * NITER + 2) norms[i] = 0.0;
}

__global__ void scatter_x0_kernel(const float* __restrict__ x0, float* __restrict__ X,
                                  __nv_bfloat16* __restrict__ Ahi, __nv_bfloat16* __restrict__ Alo) {
    int idx = blockIdx.x * blockDim.x + threadIdx.x;
    if (idx >= BSZ * D) return;
    int b = idx >> 11;
    int c = idx & (D - 1);
    float v = x0[idx];
    X[(size_t)b * LDF + c] = v;
    __nv_bfloat16 hi, lo; split32(v, hi, lo);
    Ahi[idx] = hi; Alo[idx] = lo;
}

__global__ void trace_kernel(const double* __restrict__ norms,
                             float* __restrict__ rel, float* __restrict__ absd)
{
    int k = threadIdx.x;
    if (k < NITER) {
        double a = sqrt(norms[2 * k]);
        double fn = sqrt(norms[2 * k + 1]);
        absd[k] = (float)a;
        rel[k] = (float)(a / (1e-5 + fn));
    }
}

// ---------------- host ----------------
typedef CUresult (*PFN_tmEncode)(CUtensorMap*, CUtensorMapDataType, cuuint32_t, void*,
                                 const cuuint64_t*, const cuuint64_t*, const cuuint32_t*,
                                 const cuuint32_t*, CUtensorMapInterleave, CUtensorMapSwizzle,
                                 CUtensorMapL2promotion, CUtensorMapFloatOOBfill);

static void make_tm(PFN_tmEncode enc, CUtensorMap* tm, void* ptr, uint32_t box1) {
    cuuint64_t dims[2] = { (cuuint64_t)D, (cuuint64_t)D };
    cuuint64_t strides[1] = { (cuuint64_t)D * sizeof(__nv_bfloat16) };
    cuuint32_t box[2] = { TKt, box1 };
    cuuint32_t es[2] = { 1, 1 };
    enc(tm, CU_TENSOR_MAP_DATA_TYPE_BFLOAT16, 2, ptr, dims, strides, box, es,
        CU_TENSOR_MAP_INTERLEAVE_NONE, CU_TENSOR_MAP_SWIZZLE_128B,
        CU_TENSOR_MAP_L2_PROMOTION_L2_128B, CU_TENSOR_MAP_FLOAT_OOB_FILL_NONE);
}

extern "C" void kernel_launch(void* const* d_in, const int* in_sizes, int n_in,
                              void* d_out, int out_size)
{
    const float* x0   = (const float*)d_in[0];
    const float* W    = (const float*)d_in[1];
    const float* bias = (const float*)d_in[2];

    float* out = (float*)d_out;
    float* res  = out;
    float* X    = out + (size_t)BSZ * D;
    float* rel  = out + (size_t)BSZ * D + (size_t)BSZ * MM * D;
    float* absd = rel + NITER;

    float *Fp, *Gp, *alphap; __nv_bfloat16 *Ahip, *Alop, *Whip, *Wlop;
    double* normsp;
    cudaGetSymbolAddress((void**)&Fp, g_F);
    cudaGetSymbolAddress((void**)&Gp, g_G);
    cudaGetSymbolAddress((void**)&Ahip, g_Ahi);
    cudaGetSymbolAddress((void**)&Alop, g_Alo);
    cudaGetSymbolAddress((void**)&Whip, g_Whi);
    cudaGetSymbolAddress((void**)&Wlop, g_Wlo);
    cudaGetSymbolAddress((void**)&alphap, g_alpha);
    cudaGetSymbolAddress((void**)&normsp, g_norms);

    PFN_tmEncode enc = nullptr;
    {
        void* fp = nullptr;
        cudaDriverEntryPointQueryResult qr;
        cudaGetDriverEntryPoint("cuTensorMapEncodeTiled", &fp, cudaEnableDefault, &qr);
        enc = (PFN_tmEncode)fp;
    }
    CUtensorMap tmAhi, tmAlo, tmWhi, tmWlo;
    make_tm(enc, &tmAhi, Ahip, TMt);
    make_tm(enc, &tmAlo, Alop, TMt);
    make_tm(enc, &tmWhi, Whip, TNt);
    make_tm(enc, &tmWlo, Wlop, TNt);

    cudaFuncSetAttribute(mma_gemm_kernel, cudaFuncAttributeMaxDynamicSharedMemorySize, SMEM_TOTAL);

    zero_norms_kernel<<<1, 64>>>(normsp);

    {
        dim3 blk(32, 32), grd(D / 32, D / 32);
        wsplit_kernel<<<grd, blk>>>(W, Whip, Wlop);
    }

    scatter_x0_kernel<<<(BSZ * D + 255) / 256, 256>>>(x0, X, Ahip, Alop);
    {
        dim3 grid(D / TNt, BSZ / TMt);
        mma_gemm_kernel<<<grid, 512, SMEM_TOTAL>>>(tmAhi, tmAlo, tmWhi, tmWlo, bias,
                                                   Fp, X, Gp, nullptr, LDF);
    }

    for (int k = 1; k < THRESH; k++) {
        int n = (k < MM) ? k : MM;
        int up = k % MM;

        gram_solve_kernel<<<BSZ, 256>>>(Gp, alphap, n);
        {
            dim3 grid(2, BSZ);
            combine_kernel<<<grid, 256>>>(Fp, alphap, X, Ahip, Alop,
                                          (k == THRESH - 1) ? res : nullptr, n, up);
        }
        {
            dim3 grid(D / TNt, BSZ / TMt);
            mma_gemm_kernel<<<grid, 512, SMEM_TOTAL>>>(tmAhi, tmAlo, tmWhi, tmWlo, bias,
                                                       Fp + up * D, X + up * D, Gp + up * D,
                                                       normsp + 2 * (k - 1), LDF);
        }
    }

    trace_kernel<<<1, 32>>>(normsp, rel, absd);
}

// round 12
// speedup vs baseline: 1.2211x; 1.0341x over previous
#include <cuda_runtime.h>
#include <cuda.h>
#include <cuda_bf16.h>
#include <cstdint>

// Problem constants
#define BSZ   2048
#define D     2048
#define MM    6
#define THRESH 30
#define LAM   1.0e-4f
#define LDF   (MM*D)          // 12288
#define NITER (THRESH-1)      // 29

// GEMM tiling
#define TMt   128
#define TNt   256
#define TKt   64              // 64 bf16 = 128B rows, SW128
#define KITERS (D / TKt)      // 32
#define A_BYTES (TMt * TKt * 2)              // 16384
#define W_BYTES (TNt * TKt * 2)              // 32768
#define STAGE_BYTES (2*A_BYTES + 2*W_BYTES)  // 98304
#define SMEM_TOTAL (2*STAGE_BYTES + 2048)

// ---------------- device scratch ----------------
__device__ float         g_F[(size_t)BSZ * MM * D];
__device__ float         g_G[(size_t)BSZ * MM * D];   // G = F - X history
__device__ __nv_bfloat16 g_Ahi[(size_t)BSZ * D];
__device__ __nv_bfloat16 g_Alo[(size_t)BSZ * D];
__device__ __nv_bfloat16 g_Whi[(size_t)D * D];        // [N,K] transposed
__device__ __nv_bfloat16 g_Wlo[(size_t)D * D];
__device__ double        g_norms[2 * NITER + 2];

// ---------------- PTX helpers ----------------
__device__ __forceinline__ uint32_t smem_u32(const void* p) {
    uint32_t a;
    asm("{ .reg .u64 t; cvta.to.shared.u64 t, %1; cvt.u32.u64 %0, t; }" : "=r"(a) : "l"(p));
    return a;
}
#define MBAR_INIT(a, c) asm volatile("mbarrier.init.shared.b64 [%0], %1;" :: "r"(a), "r"(c) : "memory")
#define MBAR_EXPECT_TX(a, b) asm volatile("mbarrier.arrive.expect_tx.shared.b64 _, [%0], %1;" :: "r"(a), "r"(b) : "memory")
#define MBAR_ARRIVE(a) asm volatile("mbarrier.arrive.shared.b64 _, [%0];" :: "r"(a) : "memory")
#define MBAR_WAIT(a, ph) do { \
    uint32_t _m = (a); uint32_t _p = (ph); \
    asm volatile("{\n\t.reg .pred P1;\n\tWL_%=:\n\t" \
        "mbarrier.try_wait.parity.acquire.cta.shared::cta.b64 P1, [%0], %1, 0x989680;\n\t" \
        "@P1 bra.uni WD_%=;\n\tbra.uni WL_%=;\n\tWD_%=:\n\t}" \
        :: "r"(_m), "r"(_p) : "memory"); \
} while (0)

__device__ __forceinline__ void tma2d(uint32_t dst, const CUtensorMap* tm, int x, int y, uint32_t bar) {
    asm volatile(
        "cp.async.bulk.tensor.2d.shared::cta.global.tile.mbarrier::complete_tx::bytes "
        "[%0], [%1, {%2, %3}], [%4];"
        :: "r"(dst), "l"(tm), "r"(x), "r"(y), "r"(bar) : "memory");
}

#define LDSM4(r, addr) \
    asm volatile("ldmatrix.sync.aligned.m8n8.x4.shared.b16 {%0,%1,%2,%3}, [%4];" \
        : "=r"((r)[0]), "=r"((r)[1]), "=r"((r)[2]), "=r"((r)[3]) : "r"(addr))

#define MMA16816(d, a, b0, b1) \
    asm volatile("mma.sync.aligned.m16n8k16.row.col.f32.bf16.bf16.f32 " \
        "{%0,%1,%2,%3}, {%4,%5,%6,%7}, {%8,%9}, {%0,%1,%2,%3};" \
        : "+f"((d)[0]), "+f"((d)[1]), "+f"((d)[2]), "+f"((d)[3]) \
        : "r"((a)[0]), "r"((a)[1]), "r"((a)[2]), "r"((a)[3]), "r"(b0), "r"(b1))

__device__ __forceinline__ void split32(float v, __nv_bfloat16& hi, __nv_bfloat16& lo) {
    hi = __float2bfloat16(v);
    lo = __float2bfloat16(v - __bfloat162float(hi));
}

__device__ __forceinline__ float fast_tanh(float x) {
    float ax = fabsf(x);
    float e = __expf(2.0f * ax);
    float r = 1.0f - __fdividef(2.0f, e + 1.0f);
    return copysignf(r, x);
}

// ---------------- HMMA GEMM: F = tanh(A @ W^T + bias); G = F - X; norms ----------------
__global__ __launch_bounds__(512, 1)
void mma_gemm_kernel(const __grid_constant__ CUtensorMap tmAhi,
                     const __grid_constant__ CUtensorMap tmAlo,
                     const __grid_constant__ CUtensorMap tmWhi,
                     const __grid_constant__ CUtensorMap tmWlo,
                     const float* __restrict__ bias,
                     float* __restrict__ C,
                     const float* __restrict__ Xcur,
                     float* __restrict__ Gout,
                     double* norms_slot,
                     int ldc)
{
    extern __shared__ char smem[];
    __shared__ float red[2][16];
    const uint32_t sb = smem_u32(smem);
    const uint32_t stage0 = (sb + 1024 + 1023) & ~1023u;   // SW128 needs 1024-aligned tiles
    const int tid = threadIdx.x;
    const int lane = tid & 31;
    const int w = tid >> 5;
    const int wm = w & 3;
    const int wn = w >> 2;
    const int bm = blockIdx.y * TMt;
    const int bn = blockIdx.x * TNt;

    const uint32_t FULL[2]  = { sb,      sb + 8  };
    const uint32_t EMPTY[2] = { sb + 16, sb + 24 };

    if (tid == 0) {
        MBAR_INIT(FULL[0], 1);  MBAR_INIT(FULL[1], 1);
        MBAR_INIT(EMPTY[0], 16); MBAR_INIT(EMPTY[1], 16);
    }
    __syncthreads();

    if (tid == 0) {
        #pragma unroll
        for (int s = 0; s < 2; s++) {
            uint32_t st = stage0 + s * STAGE_BYTES;
            MBAR_EXPECT_TX(FULL[s], STAGE_BYTES);
            tma2d(st,                         &tmAhi, s * TKt, bm, FULL[s]);
            tma2d(st + A_BYTES,               &tmAlo, s * TKt, bm, FULL[s]);
            tma2d(st + 2 * A_BYTES,           &tmWhi, s * TKt, bn, FULL[s]);
            tma2d(st + 2 * A_BYTES + W_BYTES, &tmWlo, s * TKt, bn, FULL[s]);
        }
    }

    float acc[2][8][4];
    #pragma unroll
    for (int mt = 0; mt < 2; mt++)
        #pragma unroll
        for (int nt = 0; nt < 8; nt++)
            #pragma unroll
            for (int q = 0; q < 4; q++) acc[mt][nt][q] = 0.f;

    const uint32_t xorv = (uint32_t)(lane & 7) << 4;
    const uint32_t a_r = lane & 15;
    const uint32_t a_b = (uint32_t)(lane >> 4) << 4;
    const uint32_t b_r = ((uint32_t)(lane >> 4) << 3) + (lane & 7);
    const uint32_t b_b = (uint32_t)((lane >> 3) & 1) << 4;

    for (int i = 0; i < KITERS; i++) {
        const int buf = i & 1;
        const int ph = (i >> 1) & 1;
        MBAR_WAIT(FULL[buf], ph);

        const uint32_t st = stage0 + buf * STAGE_BYTES;
        const uint32_t Ahi_b = st;
        const uint32_t Alo_b = st + A_BYTES;
        const uint32_t Whi_b = st + 2 * A_BYTES;
        const uint32_t Wlo_b = st + 2 * A_BYTES + W_BYTES;

        #pragma unroll
        for (int k16 = 0; k16 < 4; k16++) {
            uint32_t ahi[2][4], alo[2][4];
            #pragma unroll
            for (int mt = 0; mt < 2; mt++) {
                uint32_t R = wm * 32 + mt * 16 + a_r;
                uint32_t B = a_b + k16 * 32;
                uint32_t off = R * 128 + (B ^ xorv);
                LDSM4(ahi[mt], Ahi_b + off);
                LDSM4(alo[mt], Alo_b + off);
            }
            #pragma unroll
            for (int p = 0; p < 4; p++) {
                uint32_t R = wn * 64 + p * 16 + b_r;
                uint32_t B = b_b + k16 * 32;
                uint32_t off = R * 128 + (B ^ xorv);
                uint32_t wh[4], wl[4];
                LDSM4(wh, Whi_b + off);
                LDSM4(wl, Wlo_b + off);
                #pragma unroll
                for (int mt = 0; mt < 2; mt++) {
                    #pragma unroll
                    for (int q = 0; q < 2; q++) {
                        float* d = acc[mt][2 * p + q];
                        MMA16816(d, ahi[mt], wh[2 * q], wh[2 * q + 1]);
                        MMA16816(d, ahi[mt], wl[2 * q], wl[2 * q + 1]);
                        MMA16816(d, alo[mt], wh[2 * q], wh[2 * q + 1]);
                    }
                }
            }
        }
        if (lane == 0) MBAR_ARRIVE(EMPTY[buf]);
        if (tid == 0 && i + 2 < KITERS) {
            MBAR_WAIT(EMPTY[buf], ph);
            MBAR_EXPECT_TX(FULL[buf], STAGE_BYTES);
            int k0 = (i + 2) * TKt;
            tma2d(st,                         &tmAhi, k0, bm, FULL[buf]);
            tma2d(st + A_BYTES,               &tmAlo, k0, bm, FULL[buf]);
            tma2d(st + 2 * A_BYTES,           &tmWhi, k0, bn, FULL[buf]);
            tma2d(st + 2 * A_BYTES + W_BYTES, &tmWlo, k0, bn, FULL[buf]);
        }
    }

    // epilogue: bias + tanh -> F; g = f - x -> G; accumulate norms
    const int r_in = lane >> 2;
    const int c_in = (lane & 3) * 2;
    float sg = 0.f, sf = 0.f;
    #pragma unroll
    for (int mt = 0; mt < 2; mt++) {
        const int row = bm + wm * 32 + mt * 16 + r_in;
        #pragma unroll
        for (int nt = 0; nt < 8; nt++) {
            const int col = bn + wn * 64 + nt * 8 + c_in;
            float2 bb = *(const float2*)(bias + col);
            float v0 = fast_tanh(acc[mt][nt][0] + bb.x);
            float v1 = fast_tanh(acc[mt][nt][1] + bb.y);
            float v2 = fast_tanh(acc[mt][nt][2] + bb.x);
            float v3 = fast_tanh(acc[mt][nt][3] + bb.y);
            size_t o0 = (size_t)row * ldc + col;
            size_t o1 = (size_t)(row + 8) * ldc + col;
            float2 x0 = *(const float2*)(Xcur + o0);
            float2 x1 = *(const float2*)(Xcur + o1);
            float g0 = v0 - x0.x, g1 = v1 - x0.y;
            float g2 = v2 - x1.x, g3 = v3 - x1.y;
            *(float2*)(C + o0) = make_float2(v0, v1);
            *(float2*)(C + o1) = make_float2(v2, v3);
            *(float2*)(Gout + o0) = make_float2(g0, g1);
            *(float2*)(Gout + o1) = make_float2(g2, g3);
            sg += g0 * g0 + g1 * g1 + g2 * g2 + g3 * g3;
            sf += v0 * v0 + v1 * v1 + v2 * v2 + v3 * v3;
        }
    }
    if (norms_slot != nullptr) {
        #pragma unroll
        for (int s = 16; s > 0; s >>= 1) {
            sg += __shfl_xor_sync(0xFFFFFFFF, sg, s);
            sf += __shfl_xor_sync(0xFFFFFFFF, sf, s);
        }
        if (lane == 0) { red[0][w] = sg; red[1][w] = sf; }
        __syncthreads();
        if (w == 0 && lane < 16) {
            float a = red[0][lane], b = red[1][lane];
            #pragma unroll
            for (int s = 8; s > 0; s >>= 1) {
                a += __shfl_xor_sync(0xFFFF, a, s);
                b += __shfl_xor_sync(0xFFFF, b, s);
            }
            if (lane == 0) {
                atomicAdd(&norms_slot[0], (double)a);
                atomicAdd(&norms_slot[1], (double)b);
            }
        }
    }
}

// ---------------- fused AA step: Gram -> register Cholesky -> combine ----------------
// one block per batch; alpha lives in every thread's registers (no global round-trip)
__global__ __launch_bounds__(256)
void step_kernel(const float* __restrict__ G, const float* __restrict__ F,
                 float* __restrict__ X,
                 __nv_bfloat16* __restrict__ Ahi, __nv_bfloat16* __restrict__ Alo,
                 float* __restrict__ res,    // may be null; written on last iteration
                 int n, int up)
{
    int b = blockIdx.x;
    const int tid = threadIdx.x;
    const float4* Gb = (const float4*)(G + (size_t)b * LDF);
    const float4* Fb = (const float4*)(F + (size_t)b * LDF);

    // phase 1: Gram dots
    float acc[21];
#pragma unroll
    for (int p = 0; p < 21; p++) acc[p] = 0.f;

#pragma unroll
    for (int rep = 0; rep < 2; rep++) {
        int c4 = tid + rep * 256;   // 0..511
        float4 g4[6];
#pragma unroll
        for (int j = 0; j < 6; j++) {
            if (j < n) g4[j] = Gb[j * 512 + c4];
            else g4[j] = make_float4(0.f, 0.f, 0.f, 0.f);
        }
        int p = 0;
#pragma unroll
        for (int i = 0; i < 6; i++)
#pragma unroll
            for (int j = i; j < 6; j++) {
                acc[p] += g4[i].x * g4[j].x + g4[i].y * g4[j].y
                        + g4[i].z * g4[j].z + g4[i].w * g4[j].w;
                p++;
            }
    }

    __shared__ float sm[256][21];
#pragma unroll
    for (int p = 0; p < 21; p++) sm[tid][p] = acc[p];
    __syncthreads();
    for (int s = 128; s > 0; s >>= 1) {
        if (tid < s) {
#pragma unroll
            for (int p = 0; p < 21; p++) sm[tid][p] += sm[tid + s][p];
        }
        __syncthreads();
    }

    // phase 2: every thread redundantly solves (static indices -> registers)
    float alpha[6];
    {
        float A[6][6];
        int p = 0;
#pragma unroll
        for (int i = 0; i < 6; i++)
#pragma unroll
            for (int j = i; j < 6; j++) {
                float v = sm[0][p++];
                if (i == j) v += LAM;
                A[i][j] = v; A[j][i] = v;
            }
#pragma unroll
        for (int c = 0; c < 6; c++) {
            if (c < n) {
                float d = A[c][c];
#pragma unroll
                for (int m = 0; m < 6; m++) if (m < c) d -= A[c][m] * A[c][m];
                d = fmaxf(d, 1e-12f);
                float lcc = sqrtf(d);
                A[c][c] = lcc;
                float inv = __fdividef(1.f, lcc);
#pragma unroll
                for (int r = 0; r < 6; r++) {
                    if (r > c && r < n) {
                        float sdot = A[r][c];
#pragma unroll
                        for (int m = 0; m < 6; m++) if (m < c) sdot -= A[r][m] * A[c][m];
                        A[r][c] = sdot * inv;
                    }
                }
            }
        }
        float y[6];
#pragma unroll
        for (int c = 0; c < 6; c++) {
            float v = 1.f;
#pragma unroll
            for (int m = 0; m < 6; m++) if (m < c) v -= A[c][m] * y[m];
            y[c] = (c < n) ? __fdividef(v, A[c][c]) : 0.f;
        }
        float z[6];
#pragma unroll
        for (int c = 5; c >= 0; c--) {
            float v = y[c];
#pragma unroll
            for (int m = 0; m < 6; m++) if (m > c) v -= A[m][c] * z[m];
            z[c] = (c < n) ? __fdividef(v, A[c][c]) : 0.f;
        }
        float ssum = z[0] + z[1] + z[2] + z[3] + z[4] + z[5];
        float invs = __fdividef(1.f, ssum);
#pragma unroll
        for (int j = 0; j < 6; j++) alpha[j] = z[j] * invs;
    }

    // phase 3: combine from global F (alpha in registers)
    float4* Xb = (float4*)(X + (size_t)b * LDF + up * D);
    __nv_bfloat162* Ah = (__nv_bfloat162*)(Ahi + (size_t)b * D);
    __nv_bfloat162* Al = (__nv_bfloat162*)(Alo + (size_t)b * D);

#pragma unroll
    for (int rep = 0; rep < 2; rep++) {
        int c4 = tid + rep * 256;
        float4 xv = make_float4(0.f, 0.f, 0.f, 0.f);
#pragma unroll
        for (int j = 0; j < 6; j++) {
            if (j < n) {
                float a = alpha[j];
                float4 f = Fb[j * 512 + c4];
                xv.x += a * f.x; xv.y += a * f.y; xv.z += a * f.z; xv.w += a * f.w;
            }
        }
        Xb[c4] = xv;
        if (res != nullptr)
            ((float4*)(res + (size_t)b * D))[c4] = xv;
        __nv_bfloat16 h0, l0, h1, l1, h2, l2, h3, l3;
        split32(xv.x, h0, l0); split32(xv.y, h1, l1);
        split32(xv.z, h2, l2); split32(xv.w, h3, l3);
        Ah[c4 * 2]     = __nv_bfloat162(h0, h1);
        Ah[c4 * 2 + 1] = __nv_bfloat162(h2, h3);
        Al[c4 * 2]     = __nv_bfloat162(l0, l1);
        Al[c4 * 2 + 1] = __nv_bfloat162(l2, l3);
    }
}

// ---------------- W transpose + bf16 split ----------------
__global__ __launch_bounds__(1024)
void wsplit_kernel(const float* __restrict__ W,
                   __nv_bfloat16* __restrict__ Whi, __nv_bfloat16* __restrict__ Wlo)
{
    __shared__ float t[32][33];
    int n0 = blockIdx.x * 32, k0 = blockIdx.y * 32;
    t[threadIdx.y][threadIdx.x] = W[(size_t)(k0 + threadIdx.y) * D + n0 + threadIdx.x];
    __syncthreads();
    float v = t[threadIdx.x][threadIdx.y];
    __nv_bfloat16 hi, lo; split32(v, hi, lo);
    size_t o = (size_t)(n0 + threadIdx.y) * D + k0 + threadIdx.x;
    Whi[o] = hi; Wlo[o] = lo;
}

// ---------------- small utility kernels ----------------
__global__ void zero_norms_kernel(double* norms) {
    int i = threadIdx.x;
    if (i < 2 * NITER + 2) norms[i] = 0.0;
}

__global__ void scatter_x0_kernel(const float* __restrict__ x0, float* __restrict__ X,
                                  __nv_bfloat16* __restrict__ Ahi, __nv_bfloat16* __restrict__ Alo) {
    int idx = blockIdx.x * blockDim.x + threadIdx.x;
    if (idx >= BSZ * D) return;
    int b = idx >> 11;
    int c = idx & (D - 1);
    float v = x0[idx];
    X[(size_t)b * LDF + c] = v;
    __nv_bfloat16 hi, lo; split32(v, hi, lo);
    Ahi[idx] = hi; Alo[idx] = lo;
}

__global__ void trace_kernel(const double* __restrict__ norms,
                             float* __restrict__ rel, float* __restrict__ absd)
{
    int k = threadIdx.x;
    if (k < NITER) {
        double a = sqrt(norms[2 * k]);
        double fn = sqrt(norms[2 * k + 1]);
        absd[k] = (float)a;
        rel[k] = (float)(a / (1e-5 + fn));
    }
}

// ---------------- host ----------------
typedef CUresult (*PFN_tmEncode)(CUtensorMap*, CUtensorMapDataType, cuuint32_t, void*,
                                 const cuuint64_t*, const cuuint64_t*, const cuuint32_t*,
                                 const cuuint32_t*, CUtensorMapInterleave, CUtensorMapSwizzle,
                                 CUtensorMapL2promotion, CUtensorMapFloatOOBfill);

static void make_tm(PFN_tmEncode enc, CUtensorMap* tm, void* ptr, uint32_t box1) {
    cuuint64_t dims[2] = { (cuuint64_t)D, (cuuint64_t)D };
    cuuint64_t strides[1] = { (cuuint64_t)D * sizeof(__nv_bfloat16) };
    cuuint32_t box[2] = { TKt, box1 };
    cuuint32_t es[2] = { 1, 1 };
    enc(tm, CU_TENSOR_MAP_DATA_TYPE_BFLOAT16, 2, ptr, dims, strides, box, es,
        CU_TENSOR_MAP_INTERLEAVE_NONE, CU_TENSOR_MAP_SWIZZLE_128B,
        CU_TENSOR_MAP_L2_PROMOTION_L2_128B, CU_TENSOR_MAP_FLOAT_OOB_FILL_NONE);
}

extern "C" void kernel_launch(void* const* d_in, const int* in_sizes, int n_in,
                              void* d_out, int out_size)
{
    const float* x0   = (const float*)d_in[0];
    const float* W    = (const float*)d_in[1];
    const float* bias = (const float*)d_in[2];

    float* out = (float*)d_out;
    float* res  = out;
    float* X    = out + (size_t)BSZ * D;
    float* rel  = out + (size_t)BSZ * D + (size_t)BSZ * MM * D;
    float* absd = rel + NITER;

    float *Fp, *Gp; __nv_bfloat16 *Ahip, *Alop, *Whip, *Wlop;
    double* normsp;
    cudaGetSymbolAddress((void**)&Fp, g_F);
    cudaGetSymbolAddress((void**)&Gp, g_G);
    cudaGetSymbolAddress((void**)&Ahip, g_Ahi);
    cudaGetSymbolAddress((void**)&Alop, g_Alo);
    cudaGetSymbolAddress((void**)&Whip, g_Whi);
    cudaGetSymbolAddress((void**)&Wlop, g_Wlo);
    cudaGetSymbolAddress((void**)&normsp, g_norms);

    PFN_tmEncode enc = nullptr;
    {
        void* fp = nullptr;
        cudaDriverEntryPointQueryResult qr;
        cudaGetDriverEntryPoint("cuTensorMapEncodeTiled", &fp, cudaEnableDefault, &qr);
        enc = (PFN_tmEncode)fp;
    }
    CUtensorMap tmAhi, tmAlo, tmWhi, tmWlo;
    make_tm(enc, &tmAhi, Ahip, TMt);
    make_tm(enc, &tmAlo, Alop, TMt);
    make_tm(enc, &tmWhi, Whip, TNt);
    make_tm(enc, &tmWlo, Wlop, TNt);

    cudaFuncSetAttribute(mma_gemm_kernel, cudaFuncAttributeMaxDynamicSharedMemorySize, SMEM_TOTAL);

    zero_norms_kernel<<<1, 64>>>(normsp);

    {
        dim3 blk(32, 32), grd(D / 32, D / 32);
        wsplit_kernel<<<grd, blk>>>(W, Whip, Wlop);
    }

    scatter_x0_kernel<<<(BSZ * D + 255) / 256, 256>>>(x0, X, Ahip, Alop);
    {
        dim3 grid(D / TNt, BSZ / TMt);
        mma_gemm_kernel<<<grid, 512, SMEM_TOTAL>>>(tmAhi, tmAlo, tmWhi, tmWlo, bias,
                                                   Fp, X, Gp, nullptr, LDF);
    }

    for (int k = 1; k < THRESH; k++) {
        int n = (k < MM) ? k : MM;
        int up = k % MM;

        step_kernel<<<BSZ, 256>>>(Gp, Fp, X, Ahip, Alop,
                                  (k == THRESH - 1) ? res : nullptr, n, up);
        {
            dim3 grid(D / TNt, BSZ / TMt);
            mma_gemm_kernel<<<grid, 512, SMEM_TOTAL>>>(tmAhi, tmAlo, tmWhi, tmWlo, bias,
                                                       Fp + up * D, X + up * D, Gp + up * D,
                                                       normsp + 2 * (k - 1), LDF);
        }
    }

    trace_kernel<<<1, 32>>>(normsp, rel, absd);
}

// round 13
// speedup vs baseline: 1.2508x; 1.0243x over previous
#include <cuda_runtime.h>
#include <cuda.h>
#include <cuda_bf16.h>
#include <cstdint>

// Problem constants
#define BSZ   2048
#define D     2048
#define MM    6
#define THRESH 30
#define LAM   1.0e-4f
#define LDF   (MM*D)          // 12288
#define NITER (THRESH-1)      // 29

// GEMM tiling
#define TMt   128
#define TNt   256
#define TKt   64              // 64 bf16 = 128B rows, SW128
#define KITERS (D / TKt)      // 32
#define A_BYTES (TMt * TKt * 2)              // 16384
#define W_BYTES (TNt * TKt * 2)              // 32768
#define STAGE_BYTES (2*A_BYTES + 2*W_BYTES)  // 98304
#define SMEM_TOTAL (2*STAGE_BYTES + 2048)

// ---------------- device scratch ----------------
__device__ float         g_F[(size_t)BSZ * MM * D];
__device__ float         g_G[(size_t)BSZ * MM * D];   // G = F - X history
__device__ __nv_bfloat16 g_Ahi[(size_t)BSZ * D];
__device__ __nv_bfloat16 g_Alo[(size_t)BSZ * D];
__device__ __nv_bfloat16 g_Whi[(size_t)D * D];        // [N,K] transposed
__device__ __nv_bfloat16 g_Wlo[(size_t)D * D];
__device__ double        g_norms[2 * NITER + 2];
__device__ unsigned      g_bar[16];                    // per-row-block barrier counters

// ---------------- PTX helpers ----------------
__device__ __forceinline__ uint32_t smem_u32(const void* p) {
    uint32_t a;
    asm("{ .reg .u64 t; cvta.to.shared.u64 t, %1; cvt.u32.u64 %0, t; }" : "=r"(a) : "l"(p));
    return a;
}
#define MBAR_INIT(a, c) asm volatile("mbarrier.init.shared.b64 [%0], %1;" :: "r"(a), "r"(c) : "memory")
#define MBAR_EXPECT_TX(a, b) asm volatile("mbarrier.arrive.expect_tx.shared.b64 _, [%0], %1;" :: "r"(a), "r"(b) : "memory")
#define MBAR_ARRIVE(a) asm volatile("mbarrier.arrive.shared.b64 _, [%0];" :: "r"(a) : "memory")
#define MBAR_WAIT(a, ph) do { \
    uint32_t _m = (a); uint32_t _p = (ph); \
    asm volatile("{\n\t.reg .pred P1;\n\tWL_%=:\n\t" \
        "mbarrier.try_wait.parity.acquire.cta.shared::cta.b64 P1, [%0], %1, 0x989680;\n\t" \
        "@P1 bra.uni WD_%=;\n\tbra.uni WL_%=;\n\tWD_%=:\n\t}" \
        :: "r"(_m), "r"(_p) : "memory"); \
} while (0)
#define FENCE_PROXY_ASYNC() asm volatile("fence.proxy.async;" ::: "memory")

__device__ __forceinline__ void tma2d(uint32_t dst, const CUtensorMap* tm, int x, int y, uint32_t bar) {
    asm volatile(
        "cp.async.bulk.tensor.2d.shared::cta.global.tile.mbarrier::complete_tx::bytes "
        "[%0], [%1, {%2, %3}], [%4];"
        :: "r"(dst), "l"(tm), "r"(x), "r"(y), "r"(bar) : "memory");
}

#define LDSM4(r, addr) \
    asm volatile("ldmatrix.sync.aligned.m8n8.x4.shared.b16 {%0,%1,%2,%3}, [%4];" \
        : "=r"((r)[0]), "=r"((r)[1]), "=r"((r)[2]), "=r"((r)[3]) : "r"(addr))

#define MMA16816(d, a, b0, b1) \
    asm volatile("mma.sync.aligned.m16n8k16.row.col.f32.bf16.bf16.f32 " \
        "{%0,%1,%2,%3}, {%4,%5,%6,%7}, {%8,%9}, {%0,%1,%2,%3};" \
        : "+f"((d)[0]), "+f"((d)[1]), "+f"((d)[2]), "+f"((d)[3]) \
        : "r"((a)[0]), "r"((a)[1]), "r"((a)[2]), "r"((a)[3]), "r"(b0), "r"(b1))

__device__ __forceinline__ void split32(float v, __nv_bfloat16& hi, __nv_bfloat16& lo) {
    hi = __float2bfloat16(v);
    lo = __float2bfloat16(v - __bfloat162float(hi));
}

__device__ __forceinline__ float fast_tanh(float x) {
    float ax = fabsf(x);
    float e = __expf(2.0f * ax);
    float r = 1.0f - __fdividef(2.0f, e + 1.0f);
    return copysignf(r, x);
}

// ---------------- fused step + HMMA GEMM ----------------
// Step phase (n>0): warp-per-batch gram -> register Cholesky -> combine for this
// CTA's 16 batches; 8-CTA row barrier; then F = tanh(A@W^T+bias), G = F - X, norms.
__global__ __launch_bounds__(512, 1)
void mma_gemm_kernel(const __grid_constant__ CUtensorMap tmAhi,
                     const __grid_constant__ CUtensorMap tmAlo,
                     const __grid_constant__ CUtensorMap tmWhi,
                     const __grid_constant__ CUtensorMap tmWlo,
                     const float* __restrict__ bias,
                     float* __restrict__ C,
                     const float* __restrict__ Xcur,
                     float* __restrict__ Gout,
                     double* norms_slot,
                     int ldc,
                     // step-phase params
                     const float* __restrict__ Gall,
                     const float* __restrict__ Fall,
                     float* __restrict__ Xall,
                     __nv_bfloat16* __restrict__ Ahi,
                     __nv_bfloat16* __restrict__ Alo,
                     float* __restrict__ res,
                     int n, int up,
                     unsigned* __restrict__ barcnt, unsigned target)
{
    extern __shared__ char smem[];
    __shared__ float red[2][16];
    const uint32_t sb = smem_u32(smem);
    const uint32_t stage0 = (sb + 1024 + 1023) & ~1023u;   // SW128 needs 1024-aligned tiles
    const int tid = threadIdx.x;
    const int lane = tid & 31;
    const int w = tid >> 5;
    const int wm = w & 3;
    const int wn = w >> 2;
    const int bm = blockIdx.y * TMt;
    const int bn = blockIdx.x * TNt;

    const uint32_t FULL[2]  = { sb,      sb + 8  };
    const uint32_t EMPTY[2] = { sb + 16, sb + 24 };

    if (tid == 0) {
        MBAR_INIT(FULL[0], 1);  MBAR_INIT(FULL[1], 1);
        MBAR_INIT(EMPTY[0], 16); MBAR_INIT(EMPTY[1], 16);
    }
    __syncthreads();

    // W prefetch (independent of step phase): expect full stage bytes now.
    if (tid == 0) {
        #pragma unroll
        for (int s = 0; s < 2; s++) {
            uint32_t st = stage0 + s * STAGE_BYTES;
            MBAR_EXPECT_TX(FULL[s], STAGE_BYTES);
            tma2d(st + 2 * A_BYTES,           &tmWhi, s * TKt, bn, FULL[s]);
            tma2d(st + 2 * A_BYTES + W_BYTES, &tmWlo, s * TKt, bn, FULL[s]);
        }
    }

    // ---------------- step phase: warp-per-batch ----------------
    if (n > 0) {
        const int b = (blockIdx.y * 8 + blockIdx.x) * 16 + w;   // gridDim.x == 8
        const float4* Gb = (const float4*)(Gall + (size_t)b * LDF);
        const float4* Fb = (const float4*)(Fall + (size_t)b * LDF);

        float acc[21];
        #pragma unroll
        for (int p = 0; p < 21; p++) acc[p] = 0.f;

        #pragma unroll 4
        for (int p = 0; p < 16; p++) {
            int c4 = lane + 32 * p;
            float4 g4[6];
            #pragma unroll
            for (int j = 0; j < 6; j++) {
                if (j < n) g4[j] = Gb[j * 512 + c4];
                else g4[j] = make_float4(0.f, 0.f, 0.f, 0.f);
            }
            int q = 0;
            #pragma unroll
            for (int i = 0; i < 6; i++)
                #pragma unroll
                for (int j = i; j < 6; j++) {
                    acc[q] += g4[i].x * g4[j].x + g4[i].y * g4[j].y
                            + g4[i].z * g4[j].z + g4[i].w * g4[j].w;
                    q++;
                }
        }
        // warp reduce all 21
        #pragma unroll
        for (int s = 16; s > 0; s >>= 1)
            #pragma unroll
            for (int p = 0; p < 21; p++)
                acc[p] += __shfl_xor_sync(0xFFFFFFFF, acc[p], s);

        // register Cholesky (static indices), every lane redundantly
        float alpha[6];
        {
            float A[6][6];
            int q = 0;
            #pragma unroll
            for (int i = 0; i < 6; i++)
                #pragma unroll
                for (int j = i; j < 6; j++) {
                    float v = acc[q++];
                    if (i == j) v += LAM;
                    A[i][j] = v; A[j][i] = v;
                }
            #pragma unroll
            for (int c = 0; c < 6; c++) {
                if (c < n) {
                    float d = A[c][c];
                    #pragma unroll
                    for (int m = 0; m < 6; m++) if (m < c) d -= A[c][m] * A[c][m];
                    d = fmaxf(d, 1e-12f);
                    float lcc = sqrtf(d);
                    A[c][c] = lcc;
                    float inv = __fdividef(1.f, lcc);
                    #pragma unroll
                    for (int r = 0; r < 6; r++) {
                        if (r > c && r < n) {
                            float sdot = A[r][c];
                            #pragma unroll
                            for (int m = 0; m < 6; m++) if (m < c) sdot -= A[r][m] * A[c][m];
                            A[r][c] = sdot * inv;
                        }
                    }
                }
            }
            float y[6];
            #pragma unroll
            for (int c = 0; c < 6; c++) {
                float v = 1.f;
                #pragma unroll
                for (int m = 0; m < 6; m++) if (m < c) v -= A[c][m] * y[m];
                y[c] = (c < n) ? __fdividef(v, A[c][c]) : 0.f;
            }
            float z[6];
            #pragma unroll
            for (int c = 5; c >= 0; c--) {
                float v = y[c];
                #pragma unroll
                for (int m = 0; m < 6; m++) if (m > c) v -= A[m][c] * z[m];
                z[c] = (c < n) ? __fdividef(v, A[c][c]) : 0.f;
            }
            float ssum = z[0] + z[1] + z[2] + z[3] + z[4] + z[5];
            float invs = __fdividef(1.f, ssum);
            #pragma unroll
            for (int j = 0; j < 6; j++) alpha[j] = z[j] * invs;
        }

        // combine -> X slot up, res (last iter), Ahi/Alo splits
        float4* Xb = (float4*)(Xall + (size_t)b * LDF + up * D);
        __nv_bfloat162* Ah = (__nv_bfloat162*)(Ahi + (size_t)b * D);
        __nv_bfloat162* Al = (__nv_bfloat162*)(Alo + (size_t)b * D);
        #pragma unroll 4
        for (int p = 0; p < 16; p++) {
            int c4 = lane + 32 * p;
            float4 xv = make_float4(0.f, 0.f, 0.f, 0.f);
            #pragma unroll
            for (int j = 0; j < 6; j++) {
                if (j < n) {
                    float a = alpha[j];
                    float4 f = Fb[j * 512 + c4];
                    xv.x += a * f.x; xv.y += a * f.y; xv.z += a * f.z; xv.w += a * f.w;
                }
            }
            Xb[c4] = xv;
            if (res != nullptr)
                ((float4*)(res + (size_t)b * D))[c4] = xv;
            __nv_bfloat16 h0, l0, h1, l1, h2, l2, h3, l3;
            split32(xv.x, h0, l0); split32(xv.y, h1, l1);
            split32(xv.z, h2, l2); split32(xv.w, h3, l3);
            Ah[c4 * 2]     = __nv_bfloat162(h0, h1);
            Ah[c4 * 2 + 1] = __nv_bfloat162(h2, h3);
            Al[c4 * 2]     = __nv_bfloat162(l0, l1);
            Al[c4 * 2 + 1] = __nv_bfloat162(l2, l3);
        }

        // row barrier: 8 CTAs sharing blockIdx.y
        __syncthreads();
        FENCE_PROXY_ASYNC();
        __threadfence();
        if (tid == 0) {
            atomicAdd(&barcnt[blockIdx.y], 1u);
            volatile unsigned* c = &barcnt[blockIdx.y];
            while (*c < target) { __nanosleep(64); }
        }
        __syncthreads();
        __threadfence();
        FENCE_PROXY_ASYNC();
    }

    // A TMA (after step/barrier)
    if (tid == 0) {
        #pragma unroll
        for (int s = 0; s < 2; s++) {
            uint32_t st = stage0 + s * STAGE_BYTES;
            tma2d(st,           &tmAhi, s * TKt, bm, FULL[s]);
            tma2d(st + A_BYTES, &tmAlo, s * TKt, bm, FULL[s]);
        }
    }

    float accm[2][8][4];
    #pragma unroll
    for (int mt = 0; mt < 2; mt++)
        #pragma unroll
        for (int nt = 0; nt < 8; nt++)
            #pragma unroll
            for (int q = 0; q < 4; q++) accm[mt][nt][q] = 0.f;

    const uint32_t xorv = (uint32_t)(lane & 7) << 4;
    const uint32_t a_r = lane & 15;
    const uint32_t a_b = (uint32_t)(lane >> 4) << 4;
    const uint32_t b_r = ((uint32_t)(lane >> 4) << 3) + (lane & 7);
    const uint32_t b_b = (uint32_t)((lane >> 3) & 1) << 4;

    for (int i = 0; i < KITERS; i++) {
        const int buf = i & 1;
        const int ph = (i >> 1) & 1;
        MBAR_WAIT(FULL[buf], ph);

        const uint32_t st = stage0 + buf * STAGE_BYTES;
        const uint32_t Ahi_b = st;
        const uint32_t Alo_b = st + A_BYTES;
        const uint32_t Whi_b = st + 2 * A_BYTES;
        const uint32_t Wlo_b = st + 2 * A_BYTES + W_BYTES;

        #pragma unroll
        for (int k16 = 0; k16 < 4; k16++) {
            uint32_t ahi[2][4], alo[2][4];
            #pragma unroll
            for (int mt = 0; mt < 2; mt++) {
                uint32_t R = wm * 32 + mt * 16 + a_r;
                uint32_t B = a_b + k16 * 32;
                uint32_t off = R * 128 + (B ^ xorv);
                LDSM4(ahi[mt], Ahi_b + off);
                LDSM4(alo[mt], Alo_b + off);
            }
            #pragma unroll
            for (int p = 0; p < 4; p++) {
                uint32_t R = wn * 64 + p * 16 + b_r;
                uint32_t B = b_b + k16 * 32;
                uint32_t off = R * 128 + (B ^ xorv);
                uint32_t wh[4], wl[4];
                LDSM4(wh, Whi_b + off);
                LDSM4(wl, Wlo_b + off);
                #pragma unroll
                for (int mt = 0; mt < 2; mt++) {
                    #pragma unroll
                    for (int q = 0; q < 2; q++) {
                        float* d = accm[mt][2 * p + q];
                        MMA16816(d, ahi[mt], wh[2 * q], wh[2 * q + 1]);
                        MMA16816(d, ahi[mt], wl[2 * q], wl[2 * q + 1]);
                        MMA16816(d, alo[mt], wh[2 * q], wh[2 * q + 1]);
                    }
                }
            }
        }
        if (lane == 0) MBAR_ARRIVE(EMPTY[buf]);
        if (tid == 0 && i + 2 < KITERS) {
            MBAR_WAIT(EMPTY[buf], ph);
            MBAR_EXPECT_TX(FULL[buf], STAGE_BYTES);
            int k0 = (i + 2) * TKt;
            tma2d(st,                         &tmAhi, k0, bm, FULL[buf]);
            tma2d(st + A_BYTES,               &tmAlo, k0, bm, FULL[buf]);
            tma2d(st + 2 * A_BYTES,           &tmWhi, k0, bn, FULL[buf]);
            tma2d(st + 2 * A_BYTES + W_BYTES, &tmWlo, k0, bn, FULL[buf]);
        }
    }

    // epilogue: bias + tanh -> F; g = f - x -> G; accumulate norms
    const int r_in = lane >> 2;
    const int c_in = (lane & 3) * 2;
    float sg = 0.f, sf = 0.f;
    #pragma unroll
    for (int mt = 0; mt < 2; mt++) {
        const int row = bm + wm * 32 + mt * 16 + r_in;
        #pragma unroll
        for (int nt = 0; nt < 8; nt++) {
            const int col = bn + wn * 64 + nt * 8 + c_in;
            float2 bb = *(const float2*)(bias + col);
            float v0 = fast_tanh(accm[mt][nt][0] + bb.x);
            float v1 = fast_tanh(accm[mt][nt][1] + bb.y);
            float v2 = fast_tanh(accm[mt][nt][2] + bb.x);
            float v3 = fast_tanh(accm[mt][nt][3] + bb.y);
            size_t o0 = (size_t)row * ldc + col;
            size_t o1 = (size_t)(row + 8) * ldc + col;
            float2 x0 = *(const float2*)(Xcur + o0);
            float2 x1 = *(const float2*)(Xcur + o1);
            float g0 = v0 - x0.x, g1 = v1 - x0.y;
            float g2 = v2 - x1.x, g3 = v3 - x1.y;
            *(float2*)(C + o0) = make_float2(v0, v1);
            *(float2*)(C + o1) = make_float2(v2, v3);
            *(float2*)(Gout + o0) = make_float2(g0, g1);
            *(float2*)(Gout + o1) = make_float2(g2, g3);
            sg += g0 * g0 + g1 * g1 + g2 * g2 + g3 * g3;
            sf += v0 * v0 + v1 * v1 + v2 * v2 + v3 * v3;
        }
    }
    if (norms_slot != nullptr) {
        #pragma unroll
        for (int s = 16; s > 0; s >>= 1) {
            sg += __shfl_xor_sync(0xFFFFFFFF, sg, s);
            sf += __shfl_xor_sync(0xFFFFFFFF, sf, s);
        }
        if (lane == 0) { red[0][w] = sg; red[1][w] = sf; }
        __syncthreads();
        if (w == 0 && lane < 16) {
            float a = red[0][lane], b = red[1][lane];
            #pragma unroll
            for (int s = 8; s > 0; s >>= 1) {
                a += __shfl_xor_sync(0xFFFF, a, s);
                b += __shfl_xor_sync(0xFFFF, b, s);
            }
            if (lane == 0) {
                atomicAdd(&norms_slot[0], (double)a);
                atomicAdd(&norms_slot[1], (double)b);
            }
        }
    }
}

// ---------------- W transpose + bf16 split ----------------
__global__ __launch_bounds__(1024)
void wsplit_kernel(const float* __restrict__ W,
                   __nv_bfloat16* __restrict__ Whi, __nv_bfloat16* __restrict__ Wlo)
{
    __shared__ float t[32][33];
    int n0 = blockIdx.x * 32, k0 = blockIdx.y * 32;
    t[threadIdx.y][threadIdx.x] = W[(size_t)(k0 + threadIdx.y) * D + n0 + threadIdx.x];
    __syncthreads();
    float v = t[threadIdx.x][threadIdx.y];
    __nv_bfloat16 hi, lo; split32(v, hi, lo);
    size_t o = (size_t)(n0 + threadIdx.y) * D + k0 + threadIdx.x;
    Whi[o] = hi; Wlo[o] = lo;
}

// ---------------- small utility kernels ----------------
__global__ void zero_norms_kernel(double* norms, unsigned* bar) {
    int i = threadIdx.x;
    if (i < 2 * NITER + 2) norms[i] = 0.0;
    if (i < 16) bar[i] = 0u;
}

__global__ void scatter_x0_kernel(const float* __restrict__ x0, float* __restrict__ X,
                                  __nv_bfloat16* __restrict__ Ahi, __nv_bfloat16* __restrict__ Alo) {
    int idx = blockIdx.x * blockDim.x + threadIdx.x;
    if (idx >= BSZ * D) return;
    int b = idx >> 11;
    int c = idx & (D - 1);
    float v = x0[idx];
    X[(size_t)b * LDF + c] = v;
    __nv_bfloat16 hi, lo; split32(v, hi, lo);
    Ahi[idx] = hi; Alo[idx] = lo;
}

__global__ void trace_kernel(const double* __restrict__ norms,
                             float* __restrict__ rel, float* __restrict__ absd)
{
    int k = threadIdx.x;
    if (k < NITER) {
        double a = sqrt(norms[2 * k]);
        double fn = sqrt(norms[2 * k + 1]);
        absd[k] = (float)a;
        rel[k] = (float)(a / (1e-5 + fn));
    }
}

// ---------------- host ----------------
typedef CUresult (*PFN_tmEncode)(CUtensorMap*, CUtensorMapDataType, cuuint32_t, void*,
                                 const cuuint64_t*, const cuuint64_t*, const cuuint32_t*,
                                 const cuuint32_t*, CUtensorMapInterleave, CUtensorMapSwizzle,
                                 CUtensorMapL2promotion, CUtensorMapFloatOOBfill);

static void make_tm(PFN_tmEncode enc, CUtensorMap* tm, void* ptr, uint32_t box1) {
    cuuint64_t dims[2] = { (cuuint64_t)D, (cuuint64_t)D };
    cuuint64_t strides[1] = { (cuuint64_t)D * sizeof(__nv_bfloat16) };
    cuuint32_t box[2] = { TKt, box1 };
    cuuint32_t es[2] = { 1, 1 };
    enc(tm, CU_TENSOR_MAP_DATA_TYPE_BFLOAT16, 2, ptr, dims, strides, box, es,
        CU_TENSOR_MAP_INTERLEAVE_NONE, CU_TENSOR_MAP_SWIZZLE_128B,
        CU_TENSOR_MAP_L2_PROMOTION_L2_128B, CU_TENSOR_MAP_FLOAT_OOB_FILL_NONE);
}

extern "C" void kernel_launch(void* const* d_in, const int* in_sizes, int n_in,
                              void* d_out, int out_size)
{
    const float* x0   = (const float*)d_in[0];
    const float* W    = (const float*)d_in[1];
    const float* bias = (const float*)d_in[2];

    float* out = (float*)d_out;
    float* res  = out;
    float* X    = out + (size_t)BSZ * D;
    float* rel  = out + (size_t)BSZ * D + (size_t)BSZ * MM * D;
    float* absd = rel + NITER;

    float *Fp, *Gp; __nv_bfloat16 *Ahip, *Alop, *Whip, *Wlop;
    double* normsp; unsigned* barp;
    cudaGetSymbolAddress((void**)&Fp, g_F);
    cudaGetSymbolAddress((void**)&Gp, g_G);
    cudaGetSymbolAddress((void**)&Ahip, g_Ahi);
    cudaGetSymbolAddress((void**)&Alop, g_Alo);
    cudaGetSymbolAddress((void**)&Whip, g_Whi);
    cudaGetSymbolAddress((void**)&Wlop, g_Wlo);
    cudaGetSymbolAddress((void**)&normsp, g_norms);
    cudaGetSymbolAddress((void**)&barp, g_bar);

    PFN_tmEncode enc = nullptr;
    {
        void* fp = nullptr;
        cudaDriverEntryPointQueryResult qr;
        cudaGetDriverEntryPoint("cuTensorMapEncodeTiled", &fp, cudaEnableDefault, &qr);
        enc = (PFN_tmEncode)fp;
    }
    CUtensorMap tmAhi, tmAlo, tmWhi, tmWlo;
    make_tm(enc, &tmAhi, Ahip, TMt);
    make_tm(enc, &tmAlo, Alop, TMt);
    make_tm(enc, &tmWhi, Whip, TNt);
    make_tm(enc, &tmWlo, Wlop, TNt);

    cudaFuncSetAttribute(mma_gemm_kernel, cudaFuncAttributeMaxDynamicSharedMemorySize, SMEM_TOTAL);

    zero_norms_kernel<<<1, 64>>>(normsp, barp);

    {
        dim3 blk(32, 32), grd(D / 32, D / 32);
        wsplit_kernel<<<grd, blk>>>(W, Whip, Wlop);
    }

    scatter_x0_kernel<<<(BSZ * D + 255) / 256, 256>>>(x0, X, Ahip, Alop);
    {
        dim3 grid(D / TNt, BSZ / TMt);
        mma_gemm_kernel<<<grid, 512, SMEM_TOTAL>>>(tmAhi, tmAlo, tmWhi, tmWlo, bias,
                                                   Fp, X, Gp, nullptr, LDF,
                                                   nullptr, nullptr, nullptr, nullptr, nullptr,
                                                   nullptr, 0, 0, barp, 0u);
    }

    for (int k = 1; k < THRESH; k++) {
        int n = (k < MM) ? k : MM;
        int up = k % MM;
        dim3 grid(D / TNt, BSZ / TMt);
        mma_gemm_kernel<<<grid, 512, SMEM_TOTAL>>>(tmAhi, tmAlo, tmWhi, tmWlo, bias,
                                                   Fp + up * D, X + up * D, Gp + up * D,
                                                   normsp + 2 * (k - 1), LDF,
                                                   Gp, Fp, X, Ahip, Alop,
                                                   (k == THRESH - 1) ? res : nullptr,
                                                   n, up, barp, (unsigned)(k * 8));
    }

    trace_kernel<<<1, 32>>>(normsp, rel, absd);
}

// round 14
// speedup vs baseline: 1.2509x; 1.0001x over previous
#include <cuda_runtime.h>
#include <cuda.h>
#include <cuda_bf16.h>
#include <cstdint>

// Problem constants
#define BSZ   2048
#define D     2048
#define MM    6
#define THRESH 30
#define LAM   1.0e-4f
#define LDF   (MM*D)          // 12288
#define NITER (THRESH-1)      // 29

// GEMM tiling
#define TMt   128
#define TNt   256
#define TKt   64              // 64 bf16 = 128B rows, SW128
#define KITERS (D / TKt)      // 32
#define A_BYTES (TMt * TKt * 2)              // 16384
#define W_BYTES (TNt * TKt * 2)              // 32768
#define STAGE_BYTES (2*A_BYTES + 2*W_BYTES)  // 98304
#define SMEM_TOTAL (2*STAGE_BYTES + 2048)

// ---------------- device scratch ----------------
__device__ float         g_F[(size_t)BSZ * MM * D];
__device__ float         g_G[(size_t)BSZ * MM * D];   // G = F - X history
__device__ __nv_bfloat16 g_Ahi[(size_t)BSZ * D];
__device__ __nv_bfloat16 g_Alo[(size_t)BSZ * D];
__device__ __nv_bfloat16 g_Whi[(size_t)D * D];        // [N,K] transposed
__device__ __nv_bfloat16 g_Wlo[(size_t)D * D];
__device__ double        g_norms[2 * NITER + 2];
__device__ unsigned      g_bar[16];                    // per-row-block barrier counters

// ---------------- PTX helpers ----------------
__device__ __forceinline__ uint32_t smem_u32(const void* p) {
    uint32_t a;
    asm("{ .reg .u64 t; cvta.to.shared.u64 t, %1; cvt.u32.u64 %0, t; }" : "=r"(a) : "l"(p));
    return a;
}
#define MBAR_INIT(a, c) asm volatile("mbarrier.init.shared.b64 [%0], %1;" :: "r"(a), "r"(c) : "memory")
#define MBAR_EXPECT_TX(a, b) asm volatile("mbarrier.arrive.expect_tx.shared.b64 _, [%0], %1;" :: "r"(a), "r"(b) : "memory")
#define MBAR_ARRIVE(a) asm volatile("mbarrier.arrive.shared.b64 _, [%0];" :: "r"(a) : "memory")
#define MBAR_WAIT(a, ph) do { \
    uint32_t _m = (a); uint32_t _p = (ph); \
    asm volatile("{\n\t.reg .pred P1;\n\tWL_%=:\n\t" \
        "mbarrier.try_wait.parity.acquire.cta.shared::cta.b64 P1, [%0], %1, 0x989680;\n\t" \
        "@P1 bra.uni WD_%=;\n\tbra.uni WL_%=;\n\tWD_%=:\n\t}" \
        :: "r"(_m), "r"(_p) : "memory"); \
} while (0)
#define FENCE_PROXY_ASYNC() asm volatile("fence.proxy.async;" ::: "memory")

__device__ __forceinline__ void tma2d(uint32_t dst, const CUtensorMap* tm, int x, int y, uint32_t bar) {
    asm volatile(
        "cp.async.bulk.tensor.2d.shared::cta.global.tile.mbarrier::complete_tx::bytes "
        "[%0], [%1, {%2, %3}], [%4];"
        :: "r"(dst), "l"(tm), "r"(x), "r"(y), "r"(bar) : "memory");
}

#define LDSM4(r, addr) \
    asm volatile("ldmatrix.sync.aligned.m8n8.x4.shared.b16 {%0,%1,%2,%3}, [%4];" \
        : "=r"((r)[0]), "=r"((r)[1]), "=r"((r)[2]), "=r"((r)[3]) : "r"(addr))

#define MMA16816(d, a, b0, b1) \
    asm volatile("mma.sync.aligned.m16n8k16.row.col.f32.bf16.bf16.f32 " \
        "{%0,%1,%2,%3}, {%4,%5,%6,%7}, {%8,%9}, {%0,%1,%2,%3};" \
        : "+f"((d)[0]), "+f"((d)[1]), "+f"((d)[2]), "+f"((d)[3]) \
        : "r"((a)[0]), "r"((a)[1]), "r"((a)[2]), "r"((a)[3]), "r"(b0), "r"(b1))

__device__ __forceinline__ void split32(float v, __nv_bfloat16& hi, __nv_bfloat16& lo) {
    hi = __float2bfloat16(v);
    lo = __float2bfloat16(v - __bfloat162float(hi));
}

__device__ __forceinline__ float fast_tanh(float x) {
    float ax = fabsf(x);
    float e = __expf(2.0f * ax);
    float r = 1.0f - __fdividef(2.0f, e + 1.0f);
    return copysignf(r, x);
}

// ---------------- persistent fused AA kernel: all 30 iterations ----------------
// grid (8, 16), 512 threads, 1 CTA/SM (128 co-resident CTAs -> spin barriers safe).
__global__ __launch_bounds__(512, 1)
void aa_persistent_kernel(const __grid_constant__ CUtensorMap tmAhi,
                          const __grid_constant__ CUtensorMap tmAlo,
                          const __grid_constant__ CUtensorMap tmWhi,
                          const __grid_constant__ CUtensorMap tmWlo,
                          const float* __restrict__ bias,
                          float* __restrict__ Fall,
                          float* __restrict__ Gall,
                          float* __restrict__ Xall,
                          __nv_bfloat16* __restrict__ Ahi,
                          __nv_bfloat16* __restrict__ Alo,
                          float* __restrict__ res,
                          double* __restrict__ norms,
                          unsigned* __restrict__ barcnt)
{
    extern __shared__ char smem[];
    __shared__ float red[2][16];
    const uint32_t sb = smem_u32(smem);
    const uint32_t stage0 = (sb + 1024 + 1023) & ~1023u;   // SW128: 1024-aligned tiles
    const int tid = threadIdx.x;
    const int lane = tid & 31;
    const int w = tid >> 5;
    const int wm = w & 3;
    const int wn = w >> 2;
    const int bm = blockIdx.y * TMt;
    const int bn = blockIdx.x * TNt;

    const uint32_t FULL[2]  = { sb,      sb + 8  };
    const uint32_t EMPTY[2] = { sb + 16, sb + 24 };

    if (tid == 0) {
        MBAR_INIT(FULL[0], 1);  MBAR_INIT(FULL[1], 1);
        MBAR_INIT(EMPTY[0], 16); MBAR_INIT(EMPTY[1], 16);
    }
    __syncthreads();

    const uint32_t xorv = (uint32_t)(lane & 7) << 4;
    const uint32_t a_r = lane & 15;
    const uint32_t a_b = (uint32_t)(lane >> 4) << 4;
    const uint32_t b_r = ((uint32_t)(lane >> 4) << 3) + (lane & 7);
    const uint32_t b_b = (uint32_t)((lane >> 3) & 1) << 4;

    unsigned target = 0;

    for (int it = 0; it < THRESH; it++) {
        const int n = (it < MM) ? it : MM;
        const int up = it % MM;
        float* C = Fall + up * D;
        const float* Xcur = Xall + up * D;
        float* Gout = Gall + up * D;
        double* norms_slot = (it > 0) ? (norms + 2 * (it - 1)) : nullptr;

        // W prefetch (independent of step phase)
        if (tid == 0) {
            #pragma unroll
            for (int s = 0; s < 2; s++) {
                uint32_t st = stage0 + s * STAGE_BYTES;
                MBAR_EXPECT_TX(FULL[s], STAGE_BYTES);
                tma2d(st + 2 * A_BYTES,           &tmWhi, s * TKt, bn, FULL[s]);
                tma2d(st + 2 * A_BYTES + W_BYTES, &tmWlo, s * TKt, bn, FULL[s]);
            }
        }

        // ---------------- step phase: warp-per-batch ----------------
        if (it > 0) {
            const int b = (blockIdx.y * 8 + blockIdx.x) * 16 + w;
            const float4* Gb = (const float4*)(Gall + (size_t)b * LDF);
            const float4* Fb = (const float4*)(Fall + (size_t)b * LDF);

            float acc[21];
            #pragma unroll
            for (int p = 0; p < 21; p++) acc[p] = 0.f;

            #pragma unroll 4
            for (int p = 0; p < 16; p++) {
                int c4 = lane + 32 * p;
                float4 g4[6];
                #pragma unroll
                for (int j = 0; j < 6; j++) {
                    if (j < n) g4[j] = Gb[j * 512 + c4];
                    else g4[j] = make_float4(0.f, 0.f, 0.f, 0.f);
                }
                int q = 0;
                #pragma unroll
                for (int i = 0; i < 6; i++)
                    #pragma unroll
                    for (int j = i; j < 6; j++) {
                        acc[q] += g4[i].x * g4[j].x + g4[i].y * g4[j].y
                                + g4[i].z * g4[j].z + g4[i].w * g4[j].w;
                        q++;
                    }
            }
            #pragma unroll
            for (int s = 16; s > 0; s >>= 1)
                #pragma unroll
                for (int p = 0; p < 21; p++)
                    acc[p] += __shfl_xor_sync(0xFFFFFFFF, acc[p], s);

            float alpha[6];
            {
                float A[6][6];
                int q = 0;
                #pragma unroll
                for (int i = 0; i < 6; i++)
                    #pragma unroll
                    for (int j = i; j < 6; j++) {
                        float v = acc[q++];
                        if (i == j) v += LAM;
                        A[i][j] = v; A[j][i] = v;
                    }
                #pragma unroll
                for (int c = 0; c < 6; c++) {
                    if (c < n) {
                        float d = A[c][c];
                        #pragma unroll
                        for (int m = 0; m < 6; m++) if (m < c) d -= A[c][m] * A[c][m];
                        d = fmaxf(d, 1e-12f);
                        float lcc = sqrtf(d);
                        A[c][c] = lcc;
                        float inv = __fdividef(1.f, lcc);
                        #pragma unroll
                        for (int r = 0; r < 6; r++) {
                            if (r > c && r < n) {
                                float sdot = A[r][c];
                                #pragma unroll
                                for (int m = 0; m < 6; m++) if (m < c) sdot -= A[r][m] * A[c][m];
                                A[r][c] = sdot * inv;
                            }
                        }
                    }
                }
                float y[6];
                #pragma unroll
                for (int c = 0; c < 6; c++) {
                    float v = 1.f;
                    #pragma unroll
                    for (int m = 0; m < 6; m++) if (m < c) v -= A[c][m] * y[m];
                    y[c] = (c < n) ? __fdividef(v, A[c][c]) : 0.f;
                }
                float z[6];
                #pragma unroll
                for (int c = 5; c >= 0; c--) {
                    float v = y[c];
                    #pragma unroll
                    for (int m = 0; m < 6; m++) if (m > c) v -= A[m][c] * z[m];
                    z[c] = (c < n) ? __fdividef(v, A[c][c]) : 0.f;
                }
                float ssum = z[0] + z[1] + z[2] + z[3] + z[4] + z[5];
                float invs = __fdividef(1.f, ssum);
                #pragma unroll
                for (int j = 0; j < 6; j++) alpha[j] = z[j] * invs;
            }

            float4* Xb = (float4*)(Xall + (size_t)b * LDF + up * D);
            __nv_bfloat162* Ah = (__nv_bfloat162*)(Ahi + (size_t)b * D);
            __nv_bfloat162* Al = (__nv_bfloat162*)(Alo + (size_t)b * D);
            #pragma unroll 4
            for (int p = 0; p < 16; p++) {
                int c4 = lane + 32 * p;
                float4 xv = make_float4(0.f, 0.f, 0.f, 0.f);
                #pragma unroll
                for (int j = 0; j < 6; j++) {
                    if (j < n) {
                        float a = alpha[j];
                        float4 f = Fb[j * 512 + c4];
                        xv.x += a * f.x; xv.y += a * f.y; xv.z += a * f.z; xv.w += a * f.w;
                    }
                }
                Xb[c4] = xv;
                if (it == THRESH - 1)
                    ((float4*)(res + (size_t)b * D))[c4] = xv;
                __nv_bfloat16 h0, l0, h1, l1, h2, l2, h3, l3;
                split32(xv.x, h0, l0); split32(xv.y, h1, l1);
                split32(xv.z, h2, l2); split32(xv.w, h3, l3);
                Ah[c4 * 2]     = __nv_bfloat162(h0, h1);
                Ah[c4 * 2 + 1] = __nv_bfloat162(h2, h3);
                Al[c4 * 2]     = __nv_bfloat162(l0, l1);
                Al[c4 * 2 + 1] = __nv_bfloat162(l2, l3);
            }

            // row barrier: 8 CTAs sharing blockIdx.y
            __syncthreads();
            FENCE_PROXY_ASYNC();
            __threadfence();
            target += 8;
            if (tid == 0) {
                atomicAdd(&barcnt[blockIdx.y], 1u);
                volatile unsigned* c = &barcnt[blockIdx.y];
                while (*c < target) { __nanosleep(64); }
            }
            __syncthreads();
            __threadfence();
            FENCE_PROXY_ASYNC();
        }

        // A TMA (after step/barrier)
        if (tid == 0) {
            #pragma unroll
            for (int s = 0; s < 2; s++) {
                uint32_t st = stage0 + s * STAGE_BYTES;
                tma2d(st,           &tmAhi, s * TKt, bm, FULL[s]);
                tma2d(st + A_BYTES, &tmAlo, s * TKt, bm, FULL[s]);
            }
        }

        float accm[2][8][4];
        #pragma unroll
        for (int mt = 0; mt < 2; mt++)
            #pragma unroll
            for (int nt = 0; nt < 8; nt++)
                #pragma unroll
                for (int q = 0; q < 4; q++) accm[mt][nt][q] = 0.f;

        for (int i = 0; i < KITERS; i++) {
            const int buf = i & 1;
            const int ph = (i >> 1) & 1;
            MBAR_WAIT(FULL[buf], ph);

            const uint32_t st = stage0 + buf * STAGE_BYTES;
            const uint32_t Ahi_b = st;
            const uint32_t Alo_b = st + A_BYTES;
            const uint32_t Whi_b = st + 2 * A_BYTES;
            const uint32_t Wlo_b = st + 2 * A_BYTES + W_BYTES;

            #pragma unroll
            for (int k16 = 0; k16 < 4; k16++) {
                uint32_t ahi[2][4], alo[2][4];
                #pragma unroll
                for (int mt = 0; mt < 2; mt++) {
                    uint32_t R = wm * 32 + mt * 16 + a_r;
                    uint32_t B = a_b + k16 * 32;
                    uint32_t off = R * 128 + (B ^ xorv);
                    LDSM4(ahi[mt], Ahi_b + off);
                    LDSM4(alo[mt], Alo_b + off);
                }
                #pragma unroll
                for (int p = 0; p < 4; p++) {
                    uint32_t R = wn * 64 + p * 16 + b_r;
                    uint32_t B = b_b + k16 * 32;
                    uint32_t off = R * 128 + (B ^ xorv);
                    uint32_t wh[4], wl[4];
                    LDSM4(wh, Whi_b + off);
                    LDSM4(wl, Wlo_b + off);
                    #pragma unroll
                    for (int mt = 0; mt < 2; mt++) {
                        #pragma unroll
                        for (int q = 0; q < 2; q++) {
                            float* d = accm[mt][2 * p + q];
                            MMA16816(d, ahi[mt], wh[2 * q], wh[2 * q + 1]);
                            MMA16816(d, ahi[mt], wl[2 * q], wl[2 * q + 1]);
                            MMA16816(d, alo[mt], wh[2 * q], wh[2 * q + 1]);
                        }
                    }
                }
            }
            if (lane == 0) MBAR_ARRIVE(EMPTY[buf]);
            if (tid == 0 && i + 2 < KITERS) {
                MBAR_WAIT(EMPTY[buf], ph);
                MBAR_EXPECT_TX(FULL[buf], STAGE_BYTES);
                int k0 = (i + 2) * TKt;
                tma2d(st,                         &tmAhi, k0, bm, FULL[buf]);
                tma2d(st + A_BYTES,               &tmAlo, k0, bm, FULL[buf]);
                tma2d(st + 2 * A_BYTES,           &tmWhi, k0, bn, FULL[buf]);
                tma2d(st + 2 * A_BYTES + W_BYTES, &tmWlo, k0, bn, FULL[buf]);
            }
        }
        // drain the last two EMPTY phases so parity is consistent next iteration
        if (tid == 0) {
            MBAR_WAIT(EMPTY[0], ((KITERS - 2) >> 1) & 1);
            MBAR_WAIT(EMPTY[1], ((KITERS - 1) >> 1) & 1);
        }

        // epilogue: bias + tanh -> F; g = f - x -> G; norms
        const int r_in = lane >> 2;
        const int c_in = (lane & 3) * 2;
        float sg = 0.f, sf = 0.f;
        #pragma unroll
        for (int mt = 0; mt < 2; mt++) {
            const int row = bm + wm * 32 + mt * 16 + r_in;
            #pragma unroll
            for (int nt = 0; nt < 8; nt++) {
                const int col = bn + wn * 64 + nt * 8 + c_in;
                float2 bb = *(const float2*)(bias + col);
                float v0 = fast_tanh(accm[mt][nt][0] + bb.x);
                float v1 = fast_tanh(accm[mt][nt][1] + bb.y);
                float v2 = fast_tanh(accm[mt][nt][2] + bb.x);
                float v3 = fast_tanh(accm[mt][nt][3] + bb.y);
                size_t o0 = (size_t)row * LDF + col;
                size_t o1 = (size_t)(row + 8) * LDF + col;
                float2 x0 = *(const float2*)(Xcur + o0);
                float2 x1 = *(const float2*)(Xcur + o1);
                float g0 = v0 - x0.x, g1 = v1 - x0.y;
                float g2 = v2 - x1.x, g3 = v3 - x1.y;
                *(float2*)(C + o0) = make_float2(v0, v1);
                *(float2*)(C + o1) = make_float2(v2, v3);
                *(float2*)(Gout + o0) = make_float2(g0, g1);
                *(float2*)(Gout + o1) = make_float2(g2, g3);
                sg += g0 * g0 + g1 * g1 + g2 * g2 + g3 * g3;
                sf += v0 * v0 + v1 * v1 + v2 * v2 + v3 * v3;
            }
        }
        if (norms_slot != nullptr) {
            #pragma unroll
            for (int s = 16; s > 0; s >>= 1) {
                sg += __shfl_xor_sync(0xFFFFFFFF, sg, s);
                sf += __shfl_xor_sync(0xFFFFFFFF, sf, s);
            }
            if (lane == 0) { red[0][w] = sg; red[1][w] = sf; }
            __syncthreads();
            if (w == 0 && lane < 16) {
                float a = red[0][lane], b = red[1][lane];
                #pragma unroll
                for (int s = 8; s > 0; s >>= 1) {
                    a += __shfl_xor_sync(0xFFFF, a, s);
                    b += __shfl_xor_sync(0xFFFF, b, s);
                }
                if (lane == 0) {
                    atomicAdd(&norms_slot[0], (double)a);
                    atomicAdd(&norms_slot[1], (double)b);
                }
            }
        }

        // post-epilogue row barrier (F/G visible to next step)
        if (it < THRESH - 1) {
            __syncthreads();
            __threadfence();
            target += 8;
            if (tid == 0) {
                atomicAdd(&barcnt[blockIdx.y], 1u);
                volatile unsigned* c = &barcnt[blockIdx.y];
                while (*c < target) { __nanosleep(64); }
            }
            __syncthreads();
        }
    }
}

// ---------------- W transpose + bf16 split ----------------
__global__ __launch_bounds__(1024)
void wsplit_kernel(const float* __restrict__ W,
                   __nv_bfloat16* __restrict__ Whi, __nv_bfloat16* __restrict__ Wlo)
{
    __shared__ float t[32][33];
    int n0 = blockIdx.x * 32, k0 = blockIdx.y * 32;
    t[threadIdx.y][threadIdx.x] = W[(size_t)(k0 + threadIdx.y) * D + n0 + threadIdx.x];
    __syncthreads();
    float v = t[threadIdx.x][threadIdx.y];
    __nv_bfloat16 hi, lo; split32(v, hi, lo);
    size_t o = (size_t)(n0 + threadIdx.y) * D + k0 + threadIdx.x;
    Whi[o] = hi; Wlo[o] = lo;
}

// ---------------- small utility kernels ----------------
__global__ void zero_norms_kernel(double* norms, unsigned* bar) {
    int i = threadIdx.x;
    if (i < 2 * NITER + 2) norms[i] = 0.0;
    if (i < 16) bar[i] = 0u;
}

__global__ void scatter_x0_kernel(const float* __restrict__ x0, float* __restrict__ X,
                                  __nv_bfloat16* __restrict__ Ahi, __nv_bfloat16* __restrict__ Alo) {
    int idx = blockIdx.x * blockDim.x + threadIdx.x;
    if (idx >= BSZ * D) return;
    int b = idx >> 11;
    int c = idx & (D - 1);
    float v = x0[idx];
    X[(size_t)b * LDF + c] = v;
    __nv_bfloat16 hi, lo; split32(v, hi, lo);
    Ahi[idx] = hi; Alo[idx] = lo;
}

__global__ void trace_kernel(const double* __restrict__ norms,
                             float* __restrict__ rel, float* __restrict__ absd)
{
    int k = threadIdx.x;
    if (k < NITER) {
        double a = sqrt(norms[2 * k]);
        double fn = sqrt(norms[2 * k + 1]);
        absd[k] = (float)a;
        rel[k] = (float)(a / (1e-5 + fn));
    }
}

// ---------------- host ----------------
typedef CUresult (*PFN_tmEncode)(CUtensorMap*, CUtensorMapDataType, cuuint32_t, void*,
                                 const cuuint64_t*, const cuuint64_t*, const cuuint32_t*,
                                 const cuuint32_t*, CUtensorMapInterleave, CUtensorMapSwizzle,
                                 CUtensorMapL2promotion, CUtensorMapFloatOOBfill);

static void make_tm(PFN_tmEncode enc, CUtensorMap* tm, void* ptr, uint32_t box1) {
    cuuint64_t dims[2] = { (cuuint64_t)D, (cuuint64_t)D };
    cuuint64_t strides[1] = { (cuuint64_t)D * sizeof(__nv_bfloat16) };
    cuuint32_t box[2] = { TKt, box1 };
    cuuint32_t es[2] = { 1, 1 };
    enc(tm, CU_TENSOR_MAP_DATA_TYPE_BFLOAT16, 2, ptr, dims, strides, box, es,
        CU_TENSOR_MAP_INTERLEAVE_NONE, CU_TENSOR_MAP_SWIZZLE_128B,
        CU_TENSOR_MAP_L2_PROMOTION_L2_128B, CU_TENSOR_MAP_FLOAT_OOB_FILL_NONE);
}

extern "C" void kernel_launch(void* const* d_in, const int* in_sizes, int n_in,
                              void* d_out, int out_size)
{
    const float* x0   = (const float*)d_in[0];
    const float* W    = (const float*)d_in[1];
    const float* bias = (const float*)d_in[2];

    float* out = (float*)d_out;
    float* res  = out;
    float* X    = out + (size_t)BSZ * D;
    float* rel  = out + (size_t)BSZ * D + (size_t)BSZ * MM * D;
    float* absd = rel + NITER;

    float *Fp, *Gp; __nv_bfloat16 *Ahip, *Alop, *Whip, *Wlop;
    double* normsp; unsigned* barp;
    cudaGetSymbolAddress((void**)&Fp, g_F);
    cudaGetSymbolAddress((void**)&Gp, g_G);
    cudaGetSymbolAddress((void**)&Ahip, g_Ahi);
    cudaGetSymbolAddress((void**)&Alop, g_Alo);
    cudaGetSymbolAddress((void**)&Whip, g_Whi);
    cudaGetSymbolAddress((void**)&Wlop, g_Wlo);
    cudaGetSymbolAddress((void**)&normsp, g_norms);
    cudaGetSymbolAddress((void**)&barp, g_bar);

    PFN_tmEncode enc = nullptr;
    {
        void* fp = nullptr;
        cudaDriverEntryPointQueryResult qr;
        cudaGetDriverEntryPoint("cuTensorMapEncodeTiled", &fp, cudaEnableDefault, &qr);
        enc = (PFN_tmEncode)fp;
    }
    CUtensorMap tmAhi, tmAlo, tmWhi, tmWlo;
    make_tm(enc, &tmAhi, Ahip, TMt);
    make_tm(enc, &tmAlo, Alop, TMt);
    make_tm(enc, &tmWhi, Whip, TNt);
    make_tm(enc, &tmWlo, Wlop, TNt);

    cudaFuncSetAttribute(aa_persistent_kernel, cudaFuncAttributeMaxDynamicSharedMemorySize, SMEM_TOTAL);

    zero_norms_kernel<<<1, 64>>>(normsp, barp);

    {
        dim3 blk(32, 32), grd(D / 32, D / 32);
        wsplit_kernel<<<grd, blk>>>(W, Whip, Wlop);
    }

    scatter_x0_kernel<<<(BSZ * D + 255) / 256, 256>>>(x0, X, Ahip, Alop);

    {
        dim3 grid(D / TNt, BSZ / TMt);   // (8, 16) = 128 CTAs, all co-resident
        aa_persistent_kernel<<<grid, 512, SMEM_TOTAL>>>(tmAhi, tmAlo, tmWhi, tmWlo, bias,
                                                        Fp, Gp, X, Ahip, Alop, res,
                                                        normsp, barp);
    }

    trace_kernel<<<1, 32>>>(normsp, rel, absd);
}

// round 15
// speedup vs baseline: 1.2516x; 1.0005x over previous
#include <cuda_runtime.h>
#include <cuda.h>
#include <cuda_bf16.h>
#include <cstdint>

// Problem constants
#define BSZ   2048
#define D     2048
#define MM    6
#define THRESH 30
#define LAM   1.0e-4f
#define LDF   (MM*D)          // 12288
#define NITER (THRESH-1)      // 29

// GEMM tiling
#define TMt   128
#define TNt   256
#define TKt   64              // 64 bf16 = 128B rows, SW128
#define KITERS (D / TKt)      // 32
#define A_BYTES (TMt * TKt * 2)              // 16384
#define W_BYTES (TNt * TKt * 2)              // 32768
#define STAGE_BYTES (2*A_BYTES + 2*W_BYTES)  // 98304
#define SMEM_TOTAL (2*STAGE_BYTES + 2048)

// ---------------- device scratch ----------------
__device__ float         g_F[(size_t)BSZ * MM * D];
__device__ float         g_G[(size_t)BSZ * MM * D];   // G = F - X history
__device__ __nv_bfloat16 g_Ahi[(size_t)BSZ * D];
__device__ __nv_bfloat16 g_Alo[(size_t)BSZ * D];
__device__ __nv_bfloat16 g_Whi[(size_t)D * D];        // [N,K] transposed
__device__ __nv_bfloat16 g_Wlo[(size_t)D * D];
__device__ double        g_norms[2 * NITER + 2];
__device__ unsigned      g_bar[16];                    // per-row-block barrier counters

// ---------------- PTX helpers ----------------
__device__ __forceinline__ uint32_t smem_u32(const void* p) {
    uint32_t a;
    asm("{ .reg .u64 t; cvta.to.shared.u64 t, %1; cvt.u32.u64 %0, t; }" : "=r"(a) : "l"(p));
    return a;
}
#define MBAR_INIT(a, c) asm volatile("mbarrier.init.shared.b64 [%0], %1;" :: "r"(a), "r"(c) : "memory")
#define MBAR_EXPECT_TX(a, b) asm volatile("mbarrier.arrive.expect_tx.shared.b64 _, [%0], %1;" :: "r"(a), "r"(b) : "memory")
#define MBAR_ARRIVE(a) asm volatile("mbarrier.arrive.shared.b64 _, [%0];" :: "r"(a) : "memory")
#define MBAR_WAIT(a, ph) do { \
    uint32_t _m = (a); uint32_t _p = (ph); \
    asm volatile("{\n\t.reg .pred P1;\n\tWL_%=:\n\t" \
        "mbarrier.try_wait.parity.acquire.cta.shared::cta.b64 P1, [%0], %1, 0x989680;\n\t" \
        "@P1 bra.uni WD_%=;\n\tbra.uni WL_%=;\n\tWD_%=:\n\t}" \
        :: "r"(_m), "r"(_p) : "memory"); \
} while (0)
#define FENCE_PROXY_ASYNC() asm volatile("fence.proxy.async;" ::: "memory")

__device__ __forceinline__ void tma2d(uint32_t dst, const CUtensorMap* tm, int x, int y, uint32_t bar) {
    asm volatile(
        "cp.async.bulk.tensor.2d.shared::cta.global.tile.mbarrier::complete_tx::bytes "
        "[%0], [%1, {%2, %3}], [%4];"
        :: "r"(dst), "l"(tm), "r"(x), "r"(y), "r"(bar) : "memory");
}

#define LDSM4(r, addr) \
    asm volatile("ldmatrix.sync.aligned.m8n8.x4.shared.b16 {%0,%1,%2,%3}, [%4];" \
        : "=r"((r)[0]), "=r"((r)[1]), "=r"((r)[2]), "=r"((r)[3]) : "r"(addr))

#define MMA16816(d, a, b0, b1) \
    asm volatile("mma.sync.aligned.m16n8k16.row.col.f32.bf16.bf16.f32 " \
        "{%0,%1,%2,%3}, {%4,%5,%6,%7}, {%8,%9}, {%0,%1,%2,%3};" \
        : "+f"((d)[0]), "+f"((d)[1]), "+f"((d)[2]), "+f"((d)[3]) \
        : "r"((a)[0]), "r"((a)[1]), "r"((a)[2]), "r"((a)[3]), "r"(b0), "r"(b1))

__device__ __forceinline__ void split32(float v, __nv_bfloat16& hi, __nv_bfloat16& lo) {
    hi = __float2bfloat16(v);
    lo = __float2bfloat16(v - __bfloat162float(hi));
}

__device__ __forceinline__ float fast_tanh(float x) {
    float ax = fabsf(x);
    float e = __expf(2.0f * ax);
    float r = 1.0f - __fdividef(2.0f, e + 1.0f);
    return copysignf(r, x);
}

// ---------------- persistent fused AA kernel: all 30 iterations ----------------
__global__ __launch_bounds__(512, 1)
void aa_persistent_kernel(const __grid_constant__ CUtensorMap tmAhi,
                          const __grid_constant__ CUtensorMap tmAlo,
                          const __grid_constant__ CUtensorMap tmWhi,
                          const __grid_constant__ CUtensorMap tmWlo,
                          const float* __restrict__ bias,
                          float* __restrict__ Fall,
                          float* __restrict__ Gall,
                          float* __restrict__ Xall,
                          __nv_bfloat16* __restrict__ Ahi,
                          __nv_bfloat16* __restrict__ Alo,
                          float* __restrict__ res,
                          double* __restrict__ norms,
                          unsigned* __restrict__ barcnt)
{
    extern __shared__ char smem[];
    __shared__ float red[2][16];
    const uint32_t sb = smem_u32(smem);
    const uint32_t stage0 = (sb + 1024 + 1023) & ~1023u;   // SW128: 1024-aligned tiles
    const int tid = threadIdx.x;
    const int lane = tid & 31;
    const int w = tid >> 5;
    const int wm = w & 3;
    const int wn = w >> 2;
    const int bm = blockIdx.y * TMt;
    const int bn = blockIdx.x * TNt;

    const uint32_t FULL[2]  = { sb,      sb + 8  };
    const uint32_t EMPTY[2] = { sb + 16, sb + 24 };

    if (tid == 0) {
        MBAR_INIT(FULL[0], 1);  MBAR_INIT(FULL[1], 1);
        MBAR_INIT(EMPTY[0], 16); MBAR_INIT(EMPTY[1], 16);
    }
    __syncthreads();

    const uint32_t xorv = (uint32_t)(lane & 7) << 4;
    const uint32_t a_r = lane & 15;
    const uint32_t a_b = (uint32_t)(lane >> 4) << 4;
    const uint32_t b_r = ((uint32_t)(lane >> 4) << 3) + (lane & 7);
    const uint32_t b_b = (uint32_t)((lane >> 3) & 1) << 4;

    unsigned target = 0;

    for (int it = 0; it < THRESH; it++) {
        const int n = (it < MM) ? it : MM;
        const int up = it % MM;
        float* C = Fall + up * D;
        const float* Xcur = Xall + up * D;
        float* Gout = Gall + up * D;
        double* norms_slot = (it > 0) ? (norms + 2 * (it - 1)) : nullptr;

        // W prefetch (independent of step phase)
        if (tid == 0) {
            #pragma unroll
            for (int s = 0; s < 2; s++) {
                uint32_t st = stage0 + s * STAGE_BYTES;
                MBAR_EXPECT_TX(FULL[s], STAGE_BYTES);
                tma2d(st + 2 * A_BYTES,           &tmWhi, s * TKt, bn, FULL[s]);
                tma2d(st + 2 * A_BYTES + W_BYTES, &tmWlo, s * TKt, bn, FULL[s]);
            }
        }

        // ---------------- step phase: warp-per-batch ----------------
        if (it > 0) {
            const int b = (blockIdx.y * 8 + blockIdx.x) * 16 + w;
            const float4* Gb = (const float4*)(Gall + (size_t)b * LDF);
            const float4* Fb = (const float4*)(Fall + (size_t)b * LDF);

            float acc[21];
            #pragma unroll
            for (int p = 0; p < 21; p++) acc[p] = 0.f;

            #pragma unroll 4
            for (int p = 0; p < 16; p++) {
                int c4 = lane + 32 * p;
                float4 g4[6];
                #pragma unroll
                for (int j = 0; j < 6; j++) {
                    if (j < n) g4[j] = Gb[j * 512 + c4];
                    else g4[j] = make_float4(0.f, 0.f, 0.f, 0.f);
                }
                int q = 0;
                #pragma unroll
                for (int i = 0; i < 6; i++)
                    #pragma unroll
                    for (int j = i; j < 6; j++) {
                        acc[q] += g4[i].x * g4[j].x + g4[i].y * g4[j].y
                                + g4[i].z * g4[j].z + g4[i].w * g4[j].w;
                        q++;
                    }
            }
            #pragma unroll
            for (int s = 16; s > 0; s >>= 1)
                #pragma unroll
                for (int p = 0; p < 21; p++)
                    acc[p] += __shfl_xor_sync(0xFFFFFFFF, acc[p], s);

            float alpha[6];
            {
                float A[6][6];
                int q = 0;
                #pragma unroll
                for (int i = 0; i < 6; i++)
                    #pragma unroll
                    for (int j = i; j < 6; j++) {
                        float v = acc[q++];
                        if (i == j) v += LAM;
                        A[i][j] = v; A[j][i] = v;
                    }
                #pragma unroll
                for (int c = 0; c < 6; c++) {
                    if (c < n) {
                        float d = A[c][c];
                        #pragma unroll
                        for (int m = 0; m < 6; m++) if (m < c) d -= A[c][m] * A[c][m];
                        d = fmaxf(d, 1e-12f);
                        float lcc = sqrtf(d);
                        A[c][c] = lcc;
                        float inv = __fdividef(1.f, lcc);
                        #pragma unroll
                        for (int r = 0; r < 6; r++) {
                            if (r > c && r < n) {
                                float sdot = A[r][c];
                                #pragma unroll
                                for (int m = 0; m < 6; m++) if (m < c) sdot -= A[r][m] * A[c][m];
                                A[r][c] = sdot * inv;
                            }
                        }
                    }
                }
                float y[6];
                #pragma unroll
                for (int c = 0; c < 6; c++) {
                    float v = 1.f;
                    #pragma unroll
                    for (int m = 0; m < 6; m++) if (m < c) v -= A[c][m] * y[m];
                    y[c] = (c < n) ? __fdividef(v, A[c][c]) : 0.f;
                }
                float z[6];
                #pragma unroll
                for (int c = 5; c >= 0; c--) {
                    float v = y[c];
                    #pragma unroll
                    for (int m = 0; m < 6; m++) if (m > c) v -= A[m][c] * z[m];
                    z[c] = (c < n) ? __fdividef(v, A[c][c]) : 0.f;
                }
                float ssum = z[0] + z[1] + z[2] + z[3] + z[4] + z[5];
                float invs = __fdividef(1.f, ssum);
                #pragma unroll
                for (int j = 0; j < 6; j++) alpha[j] = z[j] * invs;
            }

            float4* Xb = (float4*)(Xall + (size_t)b * LDF + up * D);
            __nv_bfloat162* Ah = (__nv_bfloat162*)(Ahi + (size_t)b * D);
            __nv_bfloat162* Al = (__nv_bfloat162*)(Alo + (size_t)b * D);
            #pragma unroll 4
            for (int p = 0; p < 16; p++) {
                int c4 = lane + 32 * p;
                float4 xv = make_float4(0.f, 0.f, 0.f, 0.f);
                #pragma unroll
                for (int j = 0; j < 6; j++) {
                    if (j < n) {
                        float a = alpha[j];
                        float4 f = Fb[j * 512 + c4];
                        xv.x += a * f.x; xv.y += a * f.y; xv.z += a * f.z; xv.w += a * f.w;
                    }
                }
                Xb[c4] = xv;
                if (it == THRESH - 1)
                    ((float4*)(res + (size_t)b * D))[c4] = xv;
                __nv_bfloat16 h0, l0, h1, l1, h2, l2, h3, l3;
                split32(xv.x, h0, l0); split32(xv.y, h1, l1);
                split32(xv.z, h2, l2); split32(xv.w, h3, l3);
                Ah[c4 * 2]     = __nv_bfloat162(h0, h1);
                Ah[c4 * 2 + 1] = __nv_bfloat162(h2, h3);
                Al[c4 * 2]     = __nv_bfloat162(l0, l1);
                Al[c4 * 2 + 1] = __nv_bfloat162(l2, l3);
            }

            // row barrier: 8 CTAs sharing blockIdx.y
            __syncthreads();
            FENCE_PROXY_ASYNC();
            __threadfence();
            target += 8;
            if (tid == 0) {
                atomicAdd(&barcnt[blockIdx.y], 1u);
                volatile unsigned* c = &barcnt[blockIdx.y];
                while (*c < target) { __nanosleep(64); }
            }
            __syncthreads();
            __threadfence();
            FENCE_PROXY_ASYNC();
        }

        // A TMA (after step/barrier)
        if (tid == 0) {
            #pragma unroll
            for (int s = 0; s < 2; s++) {
                uint32_t st = stage0 + s * STAGE_BYTES;
                tma2d(st,           &tmAhi, s * TKt, bm, FULL[s]);
                tma2d(st + A_BYTES, &tmAlo, s * TKt, bm, FULL[s]);
            }
        }

        float accm[2][8][4];
        #pragma unroll
        for (int mt = 0; mt < 2; mt++)
            #pragma unroll
            for (int nt = 0; nt < 8; nt++)
                #pragma unroll
                for (int q = 0; q < 4; q++) accm[mt][nt][q] = 0.f;

        for (int i = 0; i < KITERS; i++) {
            const int buf = i & 1;
            const int ph = (i >> 1) & 1;
            MBAR_WAIT(FULL[buf], ph);

            const uint32_t st = stage0 + buf * STAGE_BYTES;
            const uint32_t Ahi_b = st;
            const uint32_t Alo_b = st + A_BYTES;
            const uint32_t Whi_b = st + 2 * A_BYTES;
            const uint32_t Wlo_b = st + 2 * A_BYTES + W_BYTES;

            #pragma unroll
            for (int k16 = 0; k16 < 4; k16++) {
                uint32_t ahi[2][4], alo[2][4];
                #pragma unroll
                for (int mt = 0; mt < 2; mt++) {
                    uint32_t R = wm * 32 + mt * 16 + a_r;
                    uint32_t B = a_b + k16 * 32;
                    uint32_t off = R * 128 + (B ^ xorv);
                    LDSM4(ahi[mt], Ahi_b + off);
                    LDSM4(alo[mt], Alo_b + off);
                }
                #pragma unroll
                for (int p = 0; p < 4; p++) {
                    uint32_t R = wn * 64 + p * 16 + b_r;
                    uint32_t B = b_b + k16 * 32;
                    uint32_t off = R * 128 + (B ^ xorv);
                    uint32_t wh[4], wl[4];
                    LDSM4(wh, Whi_b + off);
                    LDSM4(wl, Wlo_b + off);
                    // issue-order: 3 groups of 4 independent MMAs (same-acc reuse
                    // distance 1 -> 4; asm volatile preserves this order)
                    #pragma unroll
                    for (int mt = 0; mt < 2; mt++)
                        #pragma unroll
                        for (int q = 0; q < 2; q++)
                            MMA16816(accm[mt][2 * p + q], ahi[mt], wh[2 * q], wh[2 * q + 1]);
                    #pragma unroll
                    for (int mt = 0; mt < 2; mt++)
                        #pragma unroll
                        for (int q = 0; q < 2; q++)
                            MMA16816(accm[mt][2 * p + q], ahi[mt], wl[2 * q], wl[2 * q + 1]);
                    #pragma unroll
                    for (int mt = 0; mt < 2; mt++)
                        #pragma unroll
                        for (int q = 0; q < 2; q++)
                            MMA16816(accm[mt][2 * p + q], alo[mt], wh[2 * q], wh[2 * q + 1]);
                }
            }
            if (lane == 0) MBAR_ARRIVE(EMPTY[buf]);
            if (tid == 0 && i + 2 < KITERS) {
                MBAR_WAIT(EMPTY[buf], ph);
                MBAR_EXPECT_TX(FULL[buf], STAGE_BYTES);
                int k0 = (i + 2) * TKt;
                tma2d(st,                         &tmAhi, k0, bm, FULL[buf]);
                tma2d(st + A_BYTES,               &tmAlo, k0, bm, FULL[buf]);
                tma2d(st + 2 * A_BYTES,           &tmWhi, k0, bn, FULL[buf]);
                tma2d(st + 2 * A_BYTES + W_BYTES, &tmWlo, k0, bn, FULL[buf]);
            }
        }
        // drain the last two EMPTY phases so parity is consistent next iteration
        if (tid == 0) {
            MBAR_WAIT(EMPTY[0], ((KITERS - 2) >> 1) & 1);
            MBAR_WAIT(EMPTY[1], ((KITERS - 1) >> 1) & 1);
        }

        // epilogue: bias + tanh -> F; g = f - x -> G; norms
        const int r_in = lane >> 2;
        const int c_in = (lane & 3) * 2;
        float sg = 0.f, sf = 0.f;
        #pragma unroll
        for (int mt = 0; mt < 2; mt++) {
            const int row = bm + wm * 32 + mt * 16 + r_in;
            #pragma unroll
            for (int nt = 0; nt < 8; nt++) {
                const int col = bn + wn * 64 + nt * 8 + c_in;
                float2 bb = *(const float2*)(bias + col);
                float v0 = fast_tanh(accm[mt][nt][0] + bb.x);
                float v1 = fast_tanh(accm[mt][nt][1] + bb.y);
                float v2 = fast_tanh(accm[mt][nt][2] + bb.x);
                float v3 = fast_tanh(accm[mt][nt][3] + bb.y);
                size_t o0 = (size_t)row * LDF + col;
                size_t o1 = (size_t)(row + 8) * LDF + col;
                float2 x0 = *(const float2*)(Xcur + o0);
                float2 x1 = *(const float2*)(Xcur + o1);
                float g0 = v0 - x0.x, g1 = v1 - x0.y;
                float g2 = v2 - x1.x, g3 = v3 - x1.y;
                *(float2*)(C + o0) = make_float2(v0, v1);
                *(float2*)(C + o1) = make_float2(v2, v3);
                *(float2*)(Gout + o0) = make_float2(g0, g1);
                *(float2*)(Gout + o1) = make_float2(g2, g3);
                sg += g0 * g0 + g1 * g1 + g2 * g2 + g3 * g3;
                sf += v0 * v0 + v1 * v1 + v2 * v2 + v3 * v3;
            }
        }
        if (norms_slot != nullptr) {
            #pragma unroll
            for (int s = 16; s > 0; s >>= 1) {
                sg += __shfl_xor_sync(0xFFFFFFFF, sg, s);
                sf += __shfl_xor_sync(0xFFFFFFFF, sf, s);
            }
            if (lane == 0) { red[0][w] = sg; red[1][w] = sf; }
            __syncthreads();
            if (w == 0 && lane < 16) {
                float a = red[0][lane], b = red[1][lane];
                #pragma unroll
                for (int s = 8; s > 0; s >>= 1) {
                    a += __shfl_xor_sync(0xFFFF, a, s);
                    b += __shfl_xor_sync(0xFFFF, b, s);
                }
                if (lane == 0) {
                    atomicAdd(&norms_slot[0], (double)a);
                    atomicAdd(&norms_slot[1], (double)b);
                }
            }
        }

        // post-epilogue row barrier (F/G visible to next step)
        if (it < THRESH - 1) {
            __syncthreads();
            __threadfence();
            target += 8;
            if (tid == 0) {
                atomicAdd(&barcnt[blockIdx.y], 1u);
                volatile unsigned* c = &barcnt[blockIdx.y];
                while (*c < target) { __nanosleep(64); }
            }
            __syncthreads();
        }
    }
}

// ---------------- W transpose + bf16 split ----------------
__global__ __launch_bounds__(1024)
void wsplit_kernel(const float* __restrict__ W,
                   __nv_bfloat16* __restrict__ Whi, __nv_bfloat16* __restrict__ Wlo)
{
    __shared__ float t[32][33];
    int n0 = blockIdx.x * 32, k0 = blockIdx.y * 32;
    t[threadIdx.y][threadIdx.x] = W[(size_t)(k0 + threadIdx.y) * D + n0 + threadIdx.x];
    __syncthreads();
    float v = t[threadIdx.x][threadIdx.y];
    __nv_bfloat16 hi, lo; split32(v, hi, lo);
    size_t o = (size_t)(n0 + threadIdx.y) * D + k0 + threadIdx.x;
    Whi[o] = hi; Wlo[o] = lo;
}

// ---------------- small utility kernels ----------------
__global__ void zero_norms_kernel(double* norms, unsigned* bar) {
    int i = threadIdx.x;
    if (i < 2 * NITER + 2) norms[i] = 0.0;
    if (i < 16) bar[i] = 0u;
}

__global__ void scatter_x0_kernel(const float* __restrict__ x0, float* __restrict__ X,
                                  __nv_bfloat16* __restrict__ Ahi, __nv_bfloat16* __restrict__ Alo) {
    int idx = blockIdx.x * blockDim.x + threadIdx.x;
    if (idx >= BSZ * D) return;
    int b = idx >> 11;
    int c = idx & (D - 1);
    float v = x0[idx];
    X[(size_t)b * LDF + c] = v;
    __nv_bfloat16 hi, lo; split32(v, hi, lo);
    Ahi[idx] = hi; Alo[idx] = lo;
}

__global__ void trace_kernel(const double* __restrict__ norms,
                             float* __restrict__ rel, float* __restrict__ absd)
{
    int k = threadIdx.x;
    if (k < NITER) {
        double a = sqrt(norms[2 * k]);
        double fn = sqrt(norms[2 * k + 1]);
        absd[k] = (float)a;
        rel[k] = (float)(a / (1e-5 + fn));
    }
}

// ---------------- host ----------------
typedef CUresult (*PFN_tmEncode)(CUtensorMap*, CUtensorMapDataType, cuuint32_t, void*,
                                 const cuuint64_t*, const cuuint64_t*, const cuuint32_t*,
                                 const cuuint32_t*, CUtensorMapInterleave, CUtensorMapSwizzle,
                                 CUtensorMapL2promotion, CUtensorMapFloatOOBfill);

static void make_tm(PFN_tmEncode enc, CUtensorMap* tm, void* ptr, uint32_t box1) {
    cuuint64_t dims[2] = { (cuuint64_t)D, (cuuint64_t)D };
    cuuint64_t strides[1] = { (cuuint64_t)D * sizeof(__nv_bfloat16) };
    cuuint32_t box[2] = { TKt, box1 };
    cuuint32_t es[2] = { 1, 1 };
    enc(tm, CU_TENSOR_MAP_DATA_TYPE_BFLOAT16, 2, ptr, dims, strides, box, es,
        CU_TENSOR_MAP_INTERLEAVE_NONE, CU_TENSOR_MAP_SWIZZLE_128B,
        CU_TENSOR_MAP_L2_PROMOTION_L2_128B, CU_TENSOR_MAP_FLOAT_OOB_FILL_NONE);
}

extern "C" void kernel_launch(void* const* d_in, const int* in_sizes, int n_in,
                              void* d_out, int out_size)
{
    const float* x0   = (const float*)d_in[0];
    const float* W    = (const float*)d_in[1];
    const float* bias = (const float*)d_in[2];

    float* out = (float*)d_out;
    float* res  = out;
    float* X    = out + (size_t)BSZ * D;
    float* rel  = out + (size_t)BSZ * D + (size_t)BSZ * MM * D;
    float* absd = rel + NITER;

    float *Fp, *Gp; __nv_bfloat16 *Ahip, *Alop, *Whip, *Wlop;
    double* normsp; unsigned* barp;
    cudaGetSymbolAddress((void**)&Fp, g_F);
    cudaGetSymbolAddress((void**)&Gp, g_G);
    cudaGetSymbolAddress((void**)&Ahip, g_Ahi);
    cudaGetSymbolAddress((void**)&Alop, g_Alo);
    cudaGetSymbolAddress((void**)&Whip, g_Whi);
    cudaGetSymbolAddress((void**)&Wlop, g_Wlo);
    cudaGetSymbolAddress((void**)&normsp, g_norms);
    cudaGetSymbolAddress((void**)&barp, g_bar);

    PFN_tmEncode enc = nullptr;
    {
        void* fp = nullptr;
        cudaDriverEntryPointQueryResult qr;
        cudaGetDriverEntryPoint("cuTensorMapEncodeTiled", &fp, cudaEnableDefault, &qr);
        enc = (PFN_tmEncode)fp;
    }
    CUtensorMap tmAhi, tmAlo, tmWhi, tmWlo;
    make_tm(enc, &tmAhi, Ahip, TMt);
    make_tm(enc, &tmAlo, Alop, TMt);
    make_tm(enc, &tmWhi, Whip, TNt);
    make_tm(enc, &tmWlo, Wlop, TNt);

    cudaFuncSetAttribute(aa_persistent_kernel, cudaFuncAttributeMaxDynamicSharedMemorySize, SMEM_TOTAL);

    zero_norms_kernel<<<1, 64>>>(normsp, barp);

    {
        dim3 blk(32, 32), grd(D / 32, D / 32);
        wsplit_kernel<<<grd, blk>>>(W, Whip, Wlop);
    }

    scatter_x0_kernel<<<(BSZ * D + 255) / 256, 256>>>(x0, X, Ahip, Alop);

    {
        dim3 grid(D / TNt, BSZ / TMt);   // (8, 16) = 128 CTAs, all co-resident
        aa_persistent_kernel<<<grid, 512, SMEM_TOTAL>>>(tmAhi, tmAlo, tmWhi, tmWlo, bias,
                                                        Fp, Gp, X, Ahip, Alop, res,
                                                        normsp, barp);
    }

    trace_kernel<<<1, 32>>>(normsp, rel, absd);
}

// round 16
// speedup vs baseline: 1.2527x; 1.0009x over previous
#include <cuda_runtime.h>
#include <cuda.h>
#include <cuda_bf16.h>
#include <cstdint>

// Problem constants
#define BSZ   2048
#define D     2048
#define MM    6
#define THRESH 30
#define LAM   1.0e-4f
#define LDF   (MM*D)          // 12288
#define NITER (THRESH-1)      // 29

// GEMM tiling
#define TMt   128
#define TNt   256
#define TKt   64              // 64 bf16 = 128B rows, SW128
#define KITERS (D / TKt)      // 32
#define A_BYTES (TMt * TKt * 2)              // 16384
#define W_BYTES (TNt * TKt * 2)              // 32768
#define STAGE_BYTES (2*A_BYTES + 2*W_BYTES)  // 98304
#define SMEM_TOTAL (2*STAGE_BYTES + 2048)

// ---------------- device scratch ----------------
__device__ float         g_F[(size_t)BSZ * MM * D];
__device__ float         g_G[(size_t)BSZ * MM * D];   // G = F - X history
__device__ __nv_bfloat16 g_Ahi[(size_t)BSZ * D];
__device__ __nv_bfloat16 g_Alo[(size_t)BSZ * D];
__device__ __nv_bfloat16 g_Whi[(size_t)D * D];        // [N,K] transposed
__device__ __nv_bfloat16 g_Wlo[(size_t)D * D];
__device__ double        g_norms[2 * NITER + 2];
__device__ unsigned      g_bar[16];                    // per-row-block barrier counters

// ---------------- PTX helpers ----------------
__device__ __forceinline__ uint32_t smem_u32(const void* p) {
    uint32_t a;
    asm("{ .reg .u64 t; cvta.to.shared.u64 t, %1; cvt.u32.u64 %0, t; }" : "=r"(a) : "l"(p));
    return a;
}
#define MBAR_INIT(a, c) asm volatile("mbarrier.init.shared.b64 [%0], %1;" :: "r"(a), "r"(c) : "memory")
#define MBAR_EXPECT_TX(a, b) asm volatile("mbarrier.arrive.expect_tx.shared.b64 _, [%0], %1;" :: "r"(a), "r"(b) : "memory")
#define MBAR_ARRIVE(a) asm volatile("mbarrier.arrive.shared.b64 _, [%0];" :: "r"(a) : "memory")
#define MBAR_WAIT(a, ph) do { \
    uint32_t _m = (a); uint32_t _p = (ph); \
    asm volatile("{\n\t.reg .pred P1;\n\tWL_%=:\n\t" \
        "mbarrier.try_wait.parity.acquire.cta.shared::cta.b64 P1, [%0], %1, 0x989680;\n\t" \
        "@P1 bra.uni WD_%=;\n\tbra.uni WL_%=;\n\tWD_%=:\n\t}" \
        :: "r"(_m), "r"(_p) : "memory"); \
} while (0)
#define FENCE_PROXY_ASYNC() asm volatile("fence.proxy.async;" ::: "memory")

__device__ __forceinline__ void tma2d(uint32_t dst, const CUtensorMap* tm, int x, int y, uint32_t bar) {
    asm volatile(
        "cp.async.bulk.tensor.2d.shared::cta.global.tile.mbarrier::complete_tx::bytes "
        "[%0], [%1, {%2, %3}], [%4];"
        :: "r"(dst), "l"(tm), "r"(x), "r"(y), "r"(bar) : "memory");
}

// LDSM stays volatile: it reads smem and must not move above the acquire wait.
#define LDSM4(r, addr) \
    asm volatile("ldmatrix.sync.aligned.m8n8.x4.shared.b16 {%0,%1,%2,%3}, [%4];" \
        : "=r"((r)[0]), "=r"((r)[1]), "=r"((r)[2]), "=r"((r)[3]) : "r"(addr))

// MMA is a pure register op: NON-volatile so ptxas may schedule/pipeline freely.
#define MMA16816(d, a, b0, b1) \
    asm("mma.sync.aligned.m16n8k16.row.col.f32.bf16.bf16.f32 " \
        "{%0,%1,%2,%3}, {%4,%5,%6,%7}, {%8,%9}, {%0,%1,%2,%3};" \
        : "+f"((d)[0]), "+f"((d)[1]), "+f"((d)[2]), "+f"((d)[3]) \
        : "r"((a)[0]), "r"((a)[1]), "r"((a)[2]), "r"((a)[3]), "r"(b0), "r"(b1))

__device__ __forceinline__ void split32(float v, __nv_bfloat16& hi, __nv_bfloat16& lo) {
    hi = __float2bfloat16(v);
    lo = __float2bfloat16(v - __bfloat162float(hi));
}

__device__ __forceinline__ float fast_tanh(float x) {
    float ax = fabsf(x);
    float e = __expf(2.0f * ax);
    float r = 1.0f - __fdividef(2.0f, e + 1.0f);
    return copysignf(r, x);
}

// ---------------- persistent fused AA kernel: all 30 iterations ----------------
__global__ __launch_bounds__(512, 1)
void aa_persistent_kernel(const __grid_constant__ CUtensorMap tmAhi,
                          const __grid_constant__ CUtensorMap tmAlo,
                          const __grid_constant__ CUtensorMap tmWhi,
                          const __grid_constant__ CUtensorMap tmWlo,
                          const float* __restrict__ bias,
                          float* __restrict__ Fall,
                          float* __restrict__ Gall,
                          float* __restrict__ Xall,
                          __nv_bfloat16* __restrict__ Ahi,
                          __nv_bfloat16* __restrict__ Alo,
                          float* __restrict__ res,
                          double* __restrict__ norms,
                          unsigned* __restrict__ barcnt)
{
    extern __shared__ char smem[];
    __shared__ float red[2][16];
    const uint32_t sb = smem_u32(smem);
    const uint32_t stage0 = (sb + 1024 + 1023) & ~1023u;   // SW128: 1024-aligned tiles
    const int tid = threadIdx.x;
    const int lane = tid & 31;
    const int w = tid >> 5;
    const int wm = w & 3;
    const int wn = w >> 2;
    const int bm = blockIdx.y * TMt;
    const int bn = blockIdx.x * TNt;

    const uint32_t FULL[2]  = { sb,      sb + 8  };
    const uint32_t EMPTY[2] = { sb + 16, sb + 24 };

    if (tid == 0) {
        MBAR_INIT(FULL[0], 1);  MBAR_INIT(FULL[1], 1);
        MBAR_INIT(EMPTY[0], 16); MBAR_INIT(EMPTY[1], 16);
    }
    __syncthreads();

    const uint32_t xorv = (uint32_t)(lane & 7) << 4;
    const uint32_t a_r = lane & 15;
    const uint32_t a_b = (uint32_t)(lane >> 4) << 4;
    const uint32_t b_r = ((uint32_t)(lane >> 4) << 3) + (lane & 7);
    const uint32_t b_b = (uint32_t)((lane >> 3) & 1) << 4;

    unsigned target = 0;

    for (int it = 0; it < THRESH; it++) {
        const int n = (it < MM) ? it : MM;
        const int up = it % MM;
        float* C = Fall + up * D;
        const float* Xcur = Xall + up * D;
        float* Gout = Gall + up * D;
        double* norms_slot = (it > 0) ? (norms + 2 * (it - 1)) : nullptr;

        // W prefetch (independent of step phase)
        if (tid == 0) {
            #pragma unroll
            for (int s = 0; s < 2; s++) {
                uint32_t st = stage0 + s * STAGE_BYTES;
                MBAR_EXPECT_TX(FULL[s], STAGE_BYTES);
                tma2d(st + 2 * A_BYTES,           &tmWhi, s * TKt, bn, FULL[s]);
                tma2d(st + 2 * A_BYTES + W_BYTES, &tmWlo, s * TKt, bn, FULL[s]);
            }
        }

        // ---------------- step phase: warp-per-batch ----------------
        if (it > 0) {
            const int b = (blockIdx.y * 8 + blockIdx.x) * 16 + w;
            const float4* Gb = (const float4*)(Gall + (size_t)b * LDF);
            const float4* Fb = (const float4*)(Fall + (size_t)b * LDF);

            float acc[21];
            #pragma unroll
            for (int p = 0; p < 21; p++) acc[p] = 0.f;

            #pragma unroll 4
            for (int p = 0; p < 16; p++) {
                int c4 = lane + 32 * p;
                float4 g4[6];
                #pragma unroll
                for (int j = 0; j < 6; j++) {
                    if (j < n) g4[j] = Gb[j * 512 + c4];
                    else g4[j] = make_float4(0.f, 0.f, 0.f, 0.f);
                }
                int q = 0;
                #pragma unroll
                for (int i = 0; i < 6; i++)
                    #pragma unroll
                    for (int j = i; j < 6; j++) {
                        acc[q] += g4[i].x * g4[j].x + g4[i].y * g4[j].y
                                + g4[i].z * g4[j].z + g4[i].w * g4[j].w;
                        q++;
                    }
            }
            #pragma unroll
            for (int s = 16; s > 0; s >>= 1)
                #pragma unroll
                for (int p = 0; p < 21; p++)
                    acc[p] += __shfl_xor_sync(0xFFFFFFFF, acc[p], s);

            float alpha[6];
            {
                float A[6][6];
                int q = 0;
                #pragma unroll
                for (int i = 0; i < 6; i++)
                    #pragma unroll
                    for (int j = i; j < 6; j++) {
                        float v = acc[q++];
                        if (i == j) v += LAM;
                        A[i][j] = v; A[j][i] = v;
                    }
                #pragma unroll
                for (int c = 0; c < 6; c++) {
                    if (c < n) {
                        float d = A[c][c];
                        #pragma unroll
                        for (int m = 0; m < 6; m++) if (m < c) d -= A[c][m] * A[c][m];
                        d = fmaxf(d, 1e-12f);
                        float lcc = sqrtf(d);
                        A[c][c] = lcc;
                        float inv = __fdividef(1.f, lcc);
                        #pragma unroll
                        for (int r = 0; r < 6; r++) {
                            if (r > c && r < n) {
                                float sdot = A[r][c];
                                #pragma unroll
                                for (int m = 0; m < 6; m++) if (m < c) sdot -= A[r][m] * A[c][m];
                                A[r][c] = sdot * inv;
                            }
                        }
                    }
                }
                float y[6];
                #pragma unroll
                for (int c = 0; c < 6; c++) {
                    float v = 1.f;
                    #pragma unroll
                    for (int m = 0; m < 6; m++) if (m < c) v -= A[c][m] * y[m];
                    y[c] = (c < n) ? __fdividef(v, A[c][c]) : 0.f;
                }
                float z[6];
                #pragma unroll
                for (int c = 5; c >= 0; c--) {
                    float v = y[c];
                    #pragma unroll
                    for (int m = 0; m < 6; m++) if (m > c) v -= A[m][c] * z[m];
                    z[c] = (c < n) ? __fdividef(v, A[c][c]) : 0.f;
                }
                float ssum = z[0] + z[1] + z[2] + z[3] + z[4] + z[5];
                float invs = __fdividef(1.f, ssum);
                #pragma unroll
                for (int j = 0; j < 6; j++) alpha[j] = z[j] * invs;
            }

            float4* Xb = (float4*)(Xall + (size_t)b * LDF + up * D);
            __nv_bfloat162* Ah = (__nv_bfloat162*)(Ahi + (size_t)b * D);
            __nv_bfloat162* Al = (__nv_bfloat162*)(Alo + (size_t)b * D);
            #pragma unroll 4
            for (int p = 0; p < 16; p++) {
                int c4 = lane + 32 * p;
                float4 xv = make_float4(0.f, 0.f, 0.f, 0.f);
                #pragma unroll
                for (int j = 0; j < 6; j++) {
                    if (j < n) {
                        float a = alpha[j];
                        float4 f = Fb[j * 512 + c4];
                        xv.x += a * f.x; xv.y += a * f.y; xv.z += a * f.z; xv.w += a * f.w;
                    }
                }
                Xb[c4] = xv;
                if (it == THRESH - 1)
                    ((float4*)(res + (size_t)b * D))[c4] = xv;
                __nv_bfloat16 h0, l0, h1, l1, h2, l2, h3, l3;
                split32(xv.x, h0, l0); split32(xv.y, h1, l1);
                split32(xv.z, h2, l2); split32(xv.w, h3, l3);
                Ah[c4 * 2]     = __nv_bfloat162(h0, h1);
                Ah[c4 * 2 + 1] = __nv_bfloat162(h2, h3);
                Al[c4 * 2]     = __nv_bfloat162(l0, l1);
                Al[c4 * 2 + 1] = __nv_bfloat162(l2, l3);
            }

            // row barrier: 8 CTAs sharing blockIdx.y
            __syncthreads();
            FENCE_PROXY_ASYNC();
            __threadfence();
            target += 8;
            if (tid == 0) {
                atomicAdd(&barcnt[blockIdx.y], 1u);
                volatile unsigned* c = &barcnt[blockIdx.y];
                while (*c < target) { __nanosleep(64); }
            }
            __syncthreads();
            __threadfence();
            FENCE_PROXY_ASYNC();
        }

        // A TMA (after step/barrier)
        if (tid == 0) {
            #pragma unroll
            for (int s = 0; s < 2; s++) {
                uint32_t st = stage0 + s * STAGE_BYTES;
                tma2d(st,           &tmAhi, s * TKt, bm, FULL[s]);
                tma2d(st + A_BYTES, &tmAlo, s * TKt, bm, FULL[s]);
            }
        }

        float accm[2][8][4];
        #pragma unroll
        for (int mt = 0; mt < 2; mt++)
            #pragma unroll
            for (int nt = 0; nt < 8; nt++)
                #pragma unroll
                for (int q = 0; q < 4; q++) accm[mt][nt][q] = 0.f;

        for (int i = 0; i < KITERS; i++) {
            const int buf = i & 1;
            const int ph = (i >> 1) & 1;
            MBAR_WAIT(FULL[buf], ph);

            const uint32_t st = stage0 + buf * STAGE_BYTES;
            const uint32_t Ahi_b = st;
            const uint32_t Alo_b = st + A_BYTES;
            const uint32_t Whi_b = st + 2 * A_BYTES;
            const uint32_t Wlo_b = st + 2 * A_BYTES + W_BYTES;

            #pragma unroll
            for (int k16 = 0; k16 < 4; k16++) {
                uint32_t ahi[2][4], alo[2][4];
                #pragma unroll
                for (int mt = 0; mt < 2; mt++) {
                    uint32_t R = wm * 32 + mt * 16 + a_r;
                    uint32_t B = a_b + k16 * 32;
                    uint32_t off = R * 128 + (B ^ xorv);
                    LDSM4(ahi[mt], Ahi_b + off);
                    LDSM4(alo[mt], Alo_b + off);
                }
                #pragma unroll
                for (int p = 0; p < 4; p++) {
                    uint32_t R = wn * 64 + p * 16 + b_r;
                    uint32_t B = b_b + k16 * 32;
                    uint32_t off = R * 128 + (B ^ xorv);
                    uint32_t wh[4], wl[4];
                    LDSM4(wh, Whi_b + off);
                    LDSM4(wl, Wlo_b + off);
                    #pragma unroll
                    for (int mt = 0; mt < 2; mt++)
                        #pragma unroll
                        for (int q = 0; q < 2; q++)
                            MMA16816(accm[mt][2 * p + q], ahi[mt], wh[2 * q], wh[2 * q + 1]);
                    #pragma unroll
                    for (int mt = 0; mt < 2; mt++)
                        #pragma unroll
                        for (int q = 0; q < 2; q++)
                            MMA16816(accm[mt][2 * p + q], ahi[mt], wl[2 * q], wl[2 * q + 1]);
                    #pragma unroll
                    for (int mt = 0; mt < 2; mt++)
                        #pragma unroll
                        for (int q = 0; q < 2; q++)
                            MMA16816(accm[mt][2 * p + q], alo[mt], wh[2 * q], wh[2 * q + 1]);
                }
            }
            if (lane == 0) MBAR_ARRIVE(EMPTY[buf]);
            if (tid == 0 && i + 2 < KITERS) {
                MBAR_WAIT(EMPTY[buf], ph);
                MBAR_EXPECT_TX(FULL[buf], STAGE_BYTES);
                int k0 = (i + 2) * TKt;
                tma2d(st,                         &tmAhi, k0, bm, FULL[buf]);
                tma2d(st + A_BYTES,               &tmAlo, k0, bm, FULL[buf]);
                tma2d(st + 2 * A_BYTES,           &tmWhi, k0, bn, FULL[buf]);
                tma2d(st + 2 * A_BYTES + W_BYTES, &tmWlo, k0, bn, FULL[buf]);
            }
        }
        // drain the last two EMPTY phases so parity is consistent next iteration
        if (tid == 0) {
            MBAR_WAIT(EMPTY[0], ((KITERS - 2) >> 1) & 1);
            MBAR_WAIT(EMPTY[1], ((KITERS - 1) >> 1) & 1);
        }

        // epilogue: bias + tanh -> F; g = f - x -> G; norms
        const int r_in = lane >> 2;
        const int c_in = (lane & 3) * 2;
        float sg = 0.f, sf = 0.f;
        #pragma unroll
        for (int mt = 0; mt < 2; mt++) {
            const int row = bm + wm * 32 + mt * 16 + r_in;
            #pragma unroll
            for (int nt = 0; nt < 8; nt++) {
                const int col = bn + wn * 64 + nt * 8 + c_in;
                float2 bb = *(const float2*)(bias + col);
                float v0 = fast_tanh(accm[mt][nt][0] + bb.x);
                float v1 = fast_tanh(accm[mt][nt][1] + bb.y);
                float v2 = fast_tanh(accm[mt][nt][2] + bb.x);
                float v3 = fast_tanh(accm[mt][nt][3] + bb.y);
                size_t o0 = (size_t)row * LDF + col;
                size_t o1 = (size_t)(row + 8) * LDF + col;
                float2 x0 = *(const float2*)(Xcur + o0);
                float2 x1 = *(const float2*)(Xcur + o1);
                float g0 = v0 - x0.x, g1 = v1 - x0.y;
                float g2 = v2 - x1.x, g3 = v3 - x1.y;
                *(float2*)(C + o0) = make_float2(v0, v1);
                *(float2*)(C + o1) = make_float2(v2, v3);
                *(float2*)(Gout + o0) = make_float2(g0, g1);
                *(float2*)(Gout + o1) = make_float2(g2, g3);
                sg += g0 * g0 + g1 * g1 + g2 * g2 + g3 * g3;
                sf += v0 * v0 + v1 * v1 + v2 * v2 + v3 * v3;
            }
        }
        if (norms_slot != nullptr) {
            #pragma unroll
            for (int s = 16; s > 0; s >>= 1) {
                sg += __shfl_xor_sync(0xFFFFFFFF, sg, s);
                sf += __shfl_xor_sync(0xFFFFFFFF, sf, s);
            }
            if (lane == 0) { red[0][w] = sg; red[1][w] = sf; }
            __syncthreads();
            if (w == 0 && lane < 16) {
                float a = red[0][lane], b = red[1][lane];
                #pragma unroll
                for (int s = 8; s > 0; s >>= 1) {
                    a += __shfl_xor_sync(0xFFFF, a, s);
                    b += __shfl_xor_sync(0xFFFF, b, s);
                }
                if (lane == 0) {
                    atomicAdd(&norms_slot[0], (double)a);
                    atomicAdd(&norms_slot[1], (double)b);
                }
            }
        }

        // post-epilogue row barrier (F/G visible to next step)
        if (it < THRESH - 1) {
            __syncthreads();
            __threadfence();
            target += 8;
            if (tid == 0) {
                atomicAdd(&barcnt[blockIdx.y], 1u);
                volatile unsigned* c = &barcnt[blockIdx.y];
                while (*c < target) { __nanosleep(64); }
            }
            __syncthreads();
        }
    }
}

// ---------------- W transpose + bf16 split ----------------
__global__ __launch_bounds__(1024)
void wsplit_kernel(const float* __restrict__ W,
                   __nv_bfloat16* __restrict__ Whi, __nv_bfloat16* __restrict__ Wlo)
{
    __shared__ float t[32][33];
    int n0 = blockIdx.x * 32, k0 = blockIdx.y * 32;
    t[threadIdx.y][threadIdx.x] = W[(size_t)(k0 + threadIdx.y) * D + n0 + threadIdx.x];
    __syncthreads();
    float v = t[threadIdx.x][threadIdx.y];
    __nv_bfloat16 hi, lo; split32(v, hi, lo);
    size_t o = (size_t)(n0 + threadIdx.y) * D + k0 + threadIdx.x;
    Whi[o] = hi; Wlo[o] = lo;
}

// ---------------- small utility kernels ----------------
__global__ void zero_norms_kernel(double* norms, unsigned* bar) {
    int i = threadIdx.x;
    if (i < 2 * NITER + 2) norms[i] = 0.0;
    if (i < 16) bar[i] = 0u;
}

__global__ void scatter_x0_kernel(const float* __restrict__ x0, float* __restrict__ X,
                                  __nv_bfloat16* __restrict__ Ahi, __nv_bfloat16* __restrict__ Alo) {
    int idx = blockIdx.x * blockDim.x + threadIdx.x;
    if (idx >= BSZ * D) return;
    int b = idx >> 11;
    int c = idx & (D - 1);
    float v = x0[idx];
    X[(size_t)b * LDF + c] = v;
    __nv_bfloat16 hi, lo; split32(v, hi, lo);
    Ahi[idx] = hi; Alo[idx] = lo;
}

__global__ void trace_kernel(const double* __restrict__ norms,
                             float* __restrict__ rel, float* __restrict__ absd)
{
    int k = threadIdx.x;
    if (k < NITER) {
        double a = sqrt(norms[2 * k]);
        double fn = sqrt(norms[2 * k + 1]);
        absd[k] = (float)a;
        rel[k] = (float)(a / (1e-5 + fn));
    }
}

// ---------------- host ----------------
typedef CUresult (*PFN_tmEncode)(CUtensorMap*, CUtensorMapDataType, cuuint32_t, void*,
                                 const cuuint64_t*, const cuuint64_t*, const cuuint32_t*,
                                 const cuuint32_t*, CUtensorMapInterleave, CUtensorMapSwizzle,
                                 CUtensorMapL2promotion, CUtensorMapFloatOOBfill);

static void make_tm(PFN_tmEncode enc, CUtensorMap* tm, void* ptr, uint32_t box1) {
    cuuint64_t dims[2] = { (cuuint64_t)D, (cuuint64_t)D };
    cuuint64_t strides[1] = { (cuuint64_t)D * sizeof(__nv_bfloat16) };
    cuuint32_t box[2] = { TKt, box1 };
    cuuint32_t es[2] = { 1, 1 };
    enc(tm, CU_TENSOR_MAP_DATA_TYPE_BFLOAT16, 2, ptr, dims, strides, box, es,
        CU_TENSOR_MAP_INTERLEAVE_NONE, CU_TENSOR_MAP_SWIZZLE_128B,
        CU_TENSOR_MAP_L2_PROMOTION_L2_128B, CU_TENSOR_MAP_FLOAT_OOB_FILL_NONE);
}

extern "C" void kernel_launch(void* const* d_in, const int* in_sizes, int n_in,
                              void* d_out, int out_size)
{
    const float* x0   = (const float*)d_in[0];
    const float* W    = (const float*)d_in[1];
    const float* bias = (const float*)d_in[2];

    float* out = (float*)d_out;
    float* res  = out;
    float* X    = out + (size_t)BSZ * D;
    float* rel  = out + (size_t)BSZ * D + (size_t)BSZ * MM * D;
    float* absd = rel + NITER;

    float *Fp, *Gp; __nv_bfloat16 *Ahip, *Alop, *Whip, *Wlop;
    double* normsp; unsigned* barp;
    cudaGetSymbolAddress((void**)&Fp, g_F);
    cudaGetSymbolAddress((void**)&Gp, g_G);
    cudaGetSymbolAddress((void**)&Ahip, g_Ahi);
    cudaGetSymbolAddress((void**)&Alop, g_Alo);
    cudaGetSymbolAddress((void**)&Whip, g_Whi);
    cudaGetSymbolAddress((void**)&Wlop, g_Wlo);
    cudaGetSymbolAddress((void**)&normsp, g_norms);
    cudaGetSymbolAddress((void**)&barp, g_bar);

    PFN_tmEncode enc = nullptr;
    {
        void* fp = nullptr;
        cudaDriverEntryPointQueryResult qr;
        cudaGetDriverEntryPoint("cuTensorMapEncodeTiled", &fp, cudaEnableDefault, &qr);
        enc = (PFN_tmEncode)fp;
    }
    CUtensorMap tmAhi, tmAlo, tmWhi, tmWlo;
    make_tm(enc, &tmAhi, Ahip, TMt);
    make_tm(enc, &tmAlo, Alop, TMt);
    make_tm(enc, &tmWhi, Whip, TNt);
    make_tm(enc, &tmWlo, Wlop, TNt);

    cudaFuncSetAttribute(aa_persistent_kernel, cudaFuncAttributeMaxDynamicSharedMemorySize, SMEM_TOTAL);

    zero_norms_kernel<<<1, 64>>>(normsp, barp);

    {
        dim3 blk(32, 32), grd(D / 32, D / 32);
        wsplit_kernel<<<grd, blk>>>(W, Whip, Wlop);
    }

    scatter_x0_kernel<<<(BSZ * D + 255) / 256, 256>>>(x0, X, Ahip, Alop);

    {
        dim3 grid(D / TNt, BSZ / TMt);   // (8, 16) = 128 CTAs, all co-resident
        aa_persistent_kernel<<<grid, 512, SMEM_TOTAL>>>(tmAhi, tmAlo, tmWhi, tmWlo, bias,
                                                        Fp, Gp, X, Ahip, Alop, res,
                                                        normsp, barp);
    }

    trace_kernel<<<1, 32>>>(normsp, rel, absd);
}